// round 9
// baseline (speedup 1.0000x reference)
#include <cuda_runtime.h>
#include <cuda_fp16.h>
#include <math.h>
#include <stdint.h>

#define NB   16
#define SEQN 20
#define PP   1024
#define VD   256
#define HND  512
#define EMBD 300
#define CIN  776
#define DHD  128

// SMEM map (bytes): B dbuf 2x20480 @0, A dbuf 2x10240 @40960, resident 128x528B @61440
#define B_DB(b) ((b)*20480)
#define A_DB(b) (40960 + (b)*10240)
#define RES     61440
#define RSTR    528
#define SMEM_BYTES 129024

// ---------------- scratch ----------------
__device__ float g_base [NB*PP*VD];
__device__ float g_t    [NB*PP*VD];
__device__ float g_kh   [NB*PP*VD];
__device__ float g_vv   [NB*PP*VD];
__device__ float g_o    [NB*PP*VD];
__device__ float g_fea1 [NB*PP*VD];
__device__ float g_featA[NB*PP*VD];
__device__ float g_featB[NB*PP*VD];
__device__ float g_wsum9[9*HND*VD];
__device__ float g_hncon[NB*9*VD];
__device__ float g_spbase[PP*VD];
__device__ float g_qh   [SEQN*NB*VD];
__device__ float g_wr   [9*VD*VD];

// ---------------- helpers ----------------
__device__ __forceinline__ uint32_t h2u(__half2 h){ return *(uint32_t*)&h; }
__device__ __forceinline__ void mma16(float* d, const uint32_t* a, const uint32_t* b){
    asm volatile("mma.sync.aligned.m16n8k16.row.col.f32.f16.f16.f32 "
        "{%0,%1,%2,%3}, {%4,%5,%6,%7}, {%8,%9}, {%0,%1,%2,%3};"
        : "+f"(d[0]), "+f"(d[1]), "+f"(d[2]), "+f"(d[3])
        : "r"(a[0]), "r"(a[1]), "r"(a[2]), "r"(a[3]), "r"(b[0]), "r"(b[1]));
}
__device__ __forceinline__ void ldsm4(uint32_t* r, uint32_t addr){
    asm volatile("ldmatrix.sync.aligned.m8n8.x4.shared.b16 {%0,%1,%2,%3}, [%4];"
        : "=r"(r[0]), "=r"(r[1]), "=r"(r[2]), "=r"(r[3]) : "r"(addr));
}

// ---------------- precompute (validated) ----------------
__global__ void k_wsum9(const float* __restrict__ w) {
    int idx = blockIdx.x*256 + threadIdx.x;
    if (idx >= 9*HND*VD) return;
    int o = idx & 255, i = (idx >> 8) & 511, t = idx >> 17;
    int ty = t/3, tx = t%3;
    int kh0 = (ty==0)?1:0, kh1 = (ty==2)?1:2;
    int kw0 = (tx==0)?1:0, kw1 = (tx==2)?1:2;
    const float* wb = w + ((size_t)o*CIN + 264 + i)*9;
    float s = 0.f;
    for (int kh=kh0; kh<=kh1; kh++)
        for (int kw=kw0; kw<=kw1; kw++)
            s += wb[kh*3+kw];
    g_wsum9[idx] = s;
}
__global__ void k_hncon(const float* __restrict__ hn) {
    int idx = blockIdx.x*256 + threadIdx.x;
    if (idx >= NB*9*VD) return;
    int o = idx & 255, t = (idx >> 8) % 9, n = idx / (9*256);
    const float* hp = hn + (size_t)n*HND;
    const float* wp = g_wsum9 + (size_t)t*HND*VD + o;
    float s = 0.f;
    for (int i=0;i<HND;i++) s += hp[i]*wp[(size_t)i*VD];
    g_hncon[idx] = s;
}
__global__ void k_spbase(const float* __restrict__ w) {
    int idx = blockIdx.x*256 + threadIdx.x;
    if (idx >= PP*VD) return;
    int o = idx & 255, p = idx >> 8;
    int hh = p >> 5, ww = p & 31;
    float s = 0.f;
    for (int kh=0;kh<3;kh++) {
        int gh = hh+kh-1; if ((unsigned)gh >= 32u) continue;
        for (int kw=0;kw<3;kw++) {
            int gw = ww+kw-1; if ((unsigned)gw >= 32u) continue;
            float xmin = gw*0.0625f - 1.f, ymin = gh*0.0625f - 1.f;
            float xmax = xmin + 0.0625f,  ymax = ymin + 0.0625f;
            const float* wb = w + ((size_t)o*CIN + 256)*9 + kh*3+kw;
            s += xmin*wb[0] + ymin*wb[9] + xmax*wb[18] + ymax*wb[27]
               + 0.5f*(xmin+xmax)*wb[36] + 0.5f*(ymin+ymax)*wb[45]
               + 0.03125f*wb[54] + 0.03125f*wb[63];
        }
    }
    g_spbase[idx] = s;
}
__global__ void k_assemble() {
    int idx = blockIdx.x*256 + threadIdx.x;
    if (idx >= NB*PP*VD/4) return;
    int e = idx*4;
    int o = e & 255, p = (e >> 8) & 1023, n = e >> 18;
    int hh = p >> 5, ww = p & 31;
    int ty = (hh==0)?0:((hh==31)?2:1);
    int tx = (ww==0)?0:((ww==31)?2:1);
    float4 sp = *(const float4*)(g_spbase + (size_t)p*VD + o);
    float4 hc = *(const float4*)(g_hncon + ((size_t)(n*9 + ty*3+tx))*VD + o);
    float4 r; r.x=sp.x+hc.x; r.y=sp.y+hc.y; r.z=sp.z+hc.z; r.w=sp.w+hc.w;
    *(float4*)(g_base + (size_t)e) = r;
}
__global__ __launch_bounds__(256) void k_qh(const float* __restrict__ emb,
    const float* __restrict__ qw, const float* __restrict__ qb,
    const float* __restrict__ Wq, const float* __restrict__ bq) {
    __shared__ float es[304];
    __shared__ float qs[256];
    int n = blockIdx.x, s = blockIdx.y, c = threadIdx.x;
    for (int i=c; i<EMBD; i+=256) es[i] = emb[((size_t)n*SEQN+s)*EMBD + i];
    __syncthreads();
    float a = qb[c];
    const float* wr = qw + (size_t)c*EMBD;
    for (int e=0;e<EMBD;e++) a += es[e]*wr[e];
    qs[c] = fmaxf(a, 0.f);
    __syncthreads();
    float a2 = bq[c];
    const float* wr2 = Wq + (size_t)c*VD;
    for (int k=0;k<VD;k++) a2 += qs[k]*wr2[k];
    g_qh[((size_t)s*NB+n)*VD + c] = a2;
}
__global__ void k_repack(const float* __restrict__ w){
    int idx = blockIdx.x*256 + threadIdx.x;
    if (idx >= 9*VD*VD) return;
    int i = idx & 255, o = (idx >> 8) & 255, t = idx >> 16;
    g_wr[idx] = w[((size_t)o*CIN + i)*9 + t];
}
__global__ __launch_bounds__(256) void k_tr_in(const float* __restrict__ src, float* __restrict__ dst){
    __shared__ float t[32][33];
    int n = blockIdx.z, c0 = blockIdx.y*32, p0 = blockIdx.x*32;
    int i = threadIdx.x >> 5, j = threadIdx.x & 31;
    for (int r=0;r<32;r+=8)
        t[i+r][j] = src[((size_t)n*VD + c0+i+r)*PP + p0 + j];
    __syncthreads();
    for (int r=0;r<32;r+=8)
        dst[((size_t)n*PP + p0+i+r)*VD + c0 + j] = t[j][i+r];
}
__global__ __launch_bounds__(256) void k_tr_out(const float* __restrict__ src, float* __restrict__ dst){
    __shared__ float t[32][33];
    int n = blockIdx.z, c0 = blockIdx.y*32, p0 = blockIdx.x*32;
    int i = threadIdx.x >> 5, j = threadIdx.x & 31;
    for (int r=0;r<32;r+=8)
        t[i+r][j] = src[((size_t)n*PP + p0+i+r)*VD + c0 + j];
    __syncthreads();
    for (int r=0;r<32;r+=8)
        dst[((size_t)n*VD + c0+i+r)*PP + p0 + j] = t[j][i+r];
}

// ================= fused step kernels =================
// LN helper macro-free: done inline in each kernel (identical math to R8).

__global__ __launch_bounds__(512,1) void k_convkv(const float* __restrict__ fin,
    const float* __restrict__ mng, const float* __restrict__ mnb,
    const float* __restrict__ ipw, const float* __restrict__ ipb,
    const int* __restrict__ words, int s)
{
    if (__ldg(words + s) == 0) return;
    extern __shared__ char smc[];
    const int tid=threadIdx.x, lane=tid&31, w=tid>>5;
    const int wm=w&3, wn=w>>2, tg=lane&3, gp=lane>>2;
    const int row0=blockIdx.x*128, n=row0>>10, p0=row0&1023;
    const uint32_t smb=(uint32_t)__cvta_generic_to_shared(smc);
    const int a_row = wm*32 + (lane&7) + ((lane>>3)&1)*8;
    const uint32_t aK = ((lane>>4)&1)*16u;
    const uint32_t rB = (uint32_t)((wn*64 + ((lane>>4)&1)*8 + (lane&7))*80 + ((lane>>3)&1)*16);

    float acc[2][8][4];
#pragma unroll
    for(int f=0;f<2;f++)
#pragma unroll
    for(int nf=0;nf<8;nf++)
#pragma unroll
    for(int j=0;j<4;j++) acc[f][nf][j]=0.f;

    float4 ra[2], rb4[4];
    auto ldgAc=[&](int c){
#pragma unroll
        for(int i=0;i<2;i++){
            int q=tid+i*512, row=q>>3, c4=q&7;
            int tap=c>>3, kb=c&7, dh=tap/3-1, dw=tap%3-1;
            int p=p0+row, sh=(p>>5)+dh, sw=(p&31)+dw;
            float4 v=make_float4(0.f,0.f,0.f,0.f);
            if((unsigned)sh<32u && (unsigned)sw<32u)
                v=*(const float4*)(fin + ((size_t)((n<<10)+(sh<<5)+sw))*256 + kb*32 + c4*4);
            ra[i]=v;
        }
    };
    auto ldgBw=[&](const float* Wb, int k0){
#pragma unroll
        for(int i=0;i<4;i++){
            int q=tid+i*512;
            rb4[i]=*(const float4*)(Wb + (size_t)(q>>3)*256 + k0 + (q&7)*4);
        }
    };
    auto stsA=[&](int buf){
        char* As=smc+A_DB(buf);
#pragma unroll
        for(int i=0;i<2;i++){
            int q=tid+i*512;
            __half2 h0=__floats2half2_rn(ra[i].x,ra[i].y);
            __half2 h1=__floats2half2_rn(ra[i].z,ra[i].w);
            *(uint2*)(As + (q>>3)*80 + (q&7)*8)=make_uint2(h2u(h0),h2u(h1));
        }
    };
    auto stsB=[&](int buf){
        char* Bs=smc+B_DB(buf);
#pragma unroll
        for(int i=0;i<4;i++){
            int q=tid+i*512;
            __half2 h0=__floats2half2_rn(rb4[i].x,rb4[i].y);
            __half2 h1=__floats2half2_rn(rb4[i].z,rb4[i].w);
            *(uint2*)(Bs + (q>>3)*80 + (q&7)*8)=make_uint2(h2u(h0),h2u(h1));
        }
    };
    auto comp=[&](uint32_t Ab, int astr, uint32_t Bb){
#pragma unroll
        for(int kk=0;kk<2;kk++){
            uint32_t a0[4],a1[4];
            ldsm4(a0, Ab + (uint32_t)(a_row*astr) + aK + kk*32);
            ldsm4(a1, Ab + (uint32_t)((a_row+16)*astr) + aK + kk*32);
#pragma unroll
            for(int nfp=0;nfp<4;nfp++){
                uint32_t b4[4];
                ldsm4(b4, Bb + rB + nfp*16*80 + kk*32);
                mma16(acc[0][2*nfp+0], a0, &b4[0]);
                mma16(acc[1][2*nfp+0], a1, &b4[0]);
                mma16(acc[0][2*nfp+1], a0, &b4[2]);
                mma16(acc[1][2*nfp+1], a1, &b4[2]);
            }
        }
    };

    // -------- conv mainloop (72 stages) --------
    ldgAc(0); ldgBw(g_wr, 0);
    stsA(0); stsB(0);
    __syncthreads();
    for(int c=0;c<72;c++){
        if(c+1<72){ ldgAc(c+1); ldgBw(g_wr + (size_t)((c+1)>>3)*VD*VD, ((c+1)&7)*32); }
        comp(smb+A_DB(c&1), 80, smb+B_DB(c&1));
        if(c+1<72){ stsA((c+1)&1); stsB((c+1)&1); }
        __syncthreads();
    }

    // -------- conv epilogue: LN(relu(acc+base)) -> g_t + resident --------
#pragma unroll
    for(int f=0;f<2;f++)
#pragma unroll
    for(int nf=0;nf<8;nf++){
        int colb=wn*64+nf*8+2*tg;
#pragma unroll
        for(int h=0;h<2;h++){
            int row=row0+wm*32+f*16+h*8+gp;
            float2 bb=*(const float2*)(g_base+(size_t)row*256+colb);
            acc[f][nf][2*h+0]=fmaxf(acc[f][nf][2*h+0]+bb.x,0.f);
            acc[f][nf][2*h+1]=fmaxf(acc[f][nf][2*h+1]+bb.y,0.f);
        }
    }
    {
        float2* red=(float2*)smc;
#pragma unroll
        for(int f=0;f<2;f++)
#pragma unroll
        for(int h=0;h<2;h++){
            float su=0.f,sq=0.f;
#pragma unroll
            for(int nf=0;nf<8;nf++){
                float vx=acc[f][nf][2*h], vy=acc[f][nf][2*h+1];
                su+=vx+vy; sq+=vx*vx+vy*vy;
            }
            su+=__shfl_xor_sync(0xffffffffu,su,1); sq+=__shfl_xor_sync(0xffffffffu,sq,1);
            su+=__shfl_xor_sync(0xffffffffu,su,2); sq+=__shfl_xor_sync(0xffffffffu,sq,2);
            if(tg==0){ int rl=wm*32+f*16+h*8+gp; red[wn*128+rl]=make_float2(su,sq); }
        }
        __syncthreads();
#pragma unroll
        for(int f=0;f<2;f++)
#pragma unroll
        for(int h=0;h<2;h++){
            int rl=wm*32+f*16+h*8+gp;
            float S=0.f,Q=0.f;
#pragma unroll
            for(int w4=0;w4<4;w4++){ float2 v=red[w4*128+rl]; S+=v.x; Q+=v.y; }
            float m=S*(1.f/256.f), rs=rsqrtf(Q*(1.f/256.f)-m*m+1e-5f);
            int row=row0+rl;
#pragma unroll
            for(int nf=0;nf<8;nf++){
                int colb=wn*64+nf*8+2*tg;
                float2 g2=*(const float2*)(mng+colb), b2=*(const float2*)(mnb+colb);
                float ox=(acc[f][nf][2*h]-m)*rs*g2.x+b2.x;
                float oy=(acc[f][nf][2*h+1]-m)*rs*g2.y+b2.y;
                *(float2*)(g_t+(size_t)row*256+colb)=make_float2(ox,oy);
                *(__half2*)(smc+RES + rl*RSTR + colb*2)=__floats2half2_rn(ox,oy);
            }
        }
    }
    __syncthreads();

    // -------- K and V projections from resident t --------
    for(int kv=0;kv<2;kv++){
        const float* Wb = ipw + (size_t)(kv+1)*VD*VD;
        const float* bb = ipb + (kv+1)*VD;
        float* Cout = kv ? g_vv : g_kh;
#pragma unroll
        for(int f=0;f<2;f++)
#pragma unroll
        for(int nf=0;nf<8;nf++)
#pragma unroll
        for(int j=0;j<4;j++) acc[f][nf][j]=0.f;
        ldgBw(Wb, 0);
        stsB(0);
        __syncthreads();
        for(int c=0;c<8;c++){
            if(c+1<8) ldgBw(Wb, (c+1)*32);
            comp(smb+RES + c*64, RSTR, smb+B_DB(c&1));
            if(c+1<8) stsB((c+1)&1);
            __syncthreads();
        }
#pragma unroll
        for(int f=0;f<2;f++)
#pragma unroll
        for(int nf=0;nf<8;nf++){
            int colb=wn*64+nf*8+2*tg;
            float2 b2=*(const float2*)(bb+colb);
#pragma unroll
            for(int h=0;h<2;h++){
                int row=row0+wm*32+f*16+h*8+gp;
                *(float2*)(Cout+(size_t)row*256+colb)=
                    make_float2(acc[f][nf][2*h]+b2.x, acc[f][nf][2*h+1]+b2.y);
            }
        }
        __syncthreads();
    }
}

__global__ __launch_bounds__(512,1) void k_mlp(
    const float* __restrict__ wo, const float* __restrict__ bo,
    const float* __restrict__ ng, const float* __restrict__ nb,
    const float* __restrict__ w1, const float* __restrict__ b1,
    const float* __restrict__ w2, const float* __restrict__ b2v,
    const float* __restrict__ nfg, const float* __restrict__ nfb,
    const int* __restrict__ words, int s,
    const float* __restrict__ fcur, float* __restrict__ fout)
{
    extern __shared__ char smc[];
    const int tid=threadIdx.x;
    const int row0=blockIdx.x*128;
    if (__ldg(words + s) == 0){
#pragma unroll
        for (int i=0;i<16;i++){
            int q = tid + i*512;
            size_t off = (size_t)(row0 + (q>>6))*256 + (q&63)*4;
            *(float4*)(fout + off) = *(const float4*)(fcur + off);
        }
        return;
    }
    const int lane=tid&31, w=tid>>5;
    const int wm=w&3, wn=w>>2, tg=lane&3, gp=lane>>2;
    const uint32_t smb=(uint32_t)__cvta_generic_to_shared(smc);
    const int a_row = wm*32 + (lane&7) + ((lane>>3)&1)*8;
    const uint32_t aK = ((lane>>4)&1)*16u;
    const uint32_t rB = (uint32_t)((wn*64 + ((lane>>4)&1)*8 + (lane&7))*80 + ((lane>>3)&1)*16);

    float acc[2][8][4];
    float4 ra[2], rb4[4];
    auto ldgAo=[&](int c){
#pragma unroll
        for(int i=0;i<2;i++){
            int q=tid+i*512;
            ra[i]=*(const float4*)(g_o + (size_t)(row0+(q>>3))*256 + c*32 + (q&7)*4);
        }
    };
    auto ldgBw=[&](const float* Wb, int k0){
#pragma unroll
        for(int i=0;i<4;i++){
            int q=tid+i*512;
            rb4[i]=*(const float4*)(Wb + (size_t)(q>>3)*256 + k0 + (q&7)*4);
        }
    };
    auto stsA=[&](int buf){
        char* As=smc+A_DB(buf);
#pragma unroll
        for(int i=0;i<2;i++){
            int q=tid+i*512;
            __half2 h0=__floats2half2_rn(ra[i].x,ra[i].y);
            __half2 h1=__floats2half2_rn(ra[i].z,ra[i].w);
            *(uint2*)(As + (q>>3)*80 + (q&7)*8)=make_uint2(h2u(h0),h2u(h1));
        }
    };
    auto stsB=[&](int buf){
        char* Bs=smc+B_DB(buf);
#pragma unroll
        for(int i=0;i<4;i++){
            int q=tid+i*512;
            __half2 h0=__floats2half2_rn(rb4[i].x,rb4[i].y);
            __half2 h1=__floats2half2_rn(rb4[i].z,rb4[i].w);
            *(uint2*)(Bs + (q>>3)*80 + (q&7)*8)=make_uint2(h2u(h0),h2u(h1));
        }
    };
    auto comp=[&](uint32_t Ab, int astr, uint32_t Bb){
#pragma unroll
        for(int kk=0;kk<2;kk++){
            uint32_t a0[4],a1[4];
            ldsm4(a0, Ab + (uint32_t)(a_row*astr) + aK + kk*32);
            ldsm4(a1, Ab + (uint32_t)((a_row+16)*astr) + aK + kk*32);
#pragma unroll
            for(int nfp=0;nfp<4;nfp++){
                uint32_t b4[4];
                ldsm4(b4, Bb + rB + nfp*16*80 + kk*32);
                mma16(acc[0][2*nfp+0], a0, &b4[0]);
                mma16(acc[1][2*nfp+0], a1, &b4[0]);
                mma16(acc[0][2*nfp+1], a0, &b4[2]);
                mma16(acc[1][2*nfp+1], a1, &b4[2]);
            }
        }
    };
    auto zero=[&]{
#pragma unroll
        for(int f=0;f<2;f++)
#pragma unroll
        for(int nf=0;nf<8;nf++)
#pragma unroll
        for(int j=0;j<4;j++) acc[f][nf][j]=0.f;
    };

    // -------- out_proj (staged A from g_o) --------
    zero();
    ldgAo(0); ldgBw(wo, 0);
    stsA(0); stsB(0);
    __syncthreads();
    for(int c=0;c<8;c++){
        if(c+1<8){ ldgAo(c+1); ldgBw(wo, (c+1)*32); }
        comp(smb+A_DB(c&1), 80, smb+B_DB(c&1));
        if(c+1<8){ stsA((c+1)&1); stsB((c+1)&1); }
        __syncthreads();
    }
    // epilogue: fea1 = LN(acc + bo + g_t) -> g_fea1 (fp32 resid) + resident fp16
#pragma unroll
    for(int f=0;f<2;f++)
#pragma unroll
    for(int nf=0;nf<8;nf++){
        int colb=wn*64+nf*8+2*tg;
        float2 bb=*(const float2*)(bo+colb);
#pragma unroll
        for(int h=0;h<2;h++){
            int row=row0+wm*32+f*16+h*8+gp;
            float2 rr=*(const float2*)(g_t+(size_t)row*256+colb);
            acc[f][nf][2*h+0]+=bb.x+rr.x;
            acc[f][nf][2*h+1]+=bb.y+rr.y;
        }
    }
    {
        float2* red=(float2*)smc;
#pragma unroll
        for(int f=0;f<2;f++)
#pragma unroll
        for(int h=0;h<2;h++){
            float su=0.f,sq=0.f;
#pragma unroll
            for(int nf=0;nf<8;nf++){
                float vx=acc[f][nf][2*h], vy=acc[f][nf][2*h+1];
                su+=vx+vy; sq+=vx*vx+vy*vy;
            }
            su+=__shfl_xor_sync(0xffffffffu,su,1); sq+=__shfl_xor_sync(0xffffffffu,sq,1);
            su+=__shfl_xor_sync(0xffffffffu,su,2); sq+=__shfl_xor_sync(0xffffffffu,sq,2);
            if(tg==0){ int rl=wm*32+f*16+h*8+gp; red[wn*128+rl]=make_float2(su,sq); }
        }
        __syncthreads();
#pragma unroll
        for(int f=0;f<2;f++)
#pragma unroll
        for(int h=0;h<2;h++){
            int rl=wm*32+f*16+h*8+gp;
            float S=0.f,Q=0.f;
#pragma unroll
            for(int w4=0;w4<4;w4++){ float2 v=red[w4*128+rl]; S+=v.x; Q+=v.y; }
            float m=S*(1.f/256.f), rs=rsqrtf(Q*(1.f/256.f)-m*m+1e-5f);
            int row=row0+rl;
#pragma unroll
            for(int nf=0;nf<8;nf++){
                int colb=wn*64+nf*8+2*tg;
                float2 g2=*(const float2*)(ng+colb), bb2=*(const float2*)(nb+colb);
                float ox=(acc[f][nf][2*h]-m)*rs*g2.x+bb2.x;
                float oy=(acc[f][nf][2*h+1]-m)*rs*g2.y+bb2.y;
                *(float2*)(g_fea1+(size_t)row*256+colb)=make_float2(ox,oy);
                *(__half2*)(smc+RES + rl*RSTR + colb*2)=__floats2half2_rn(ox,oy);
            }
        }
    }
    __syncthreads();

    // -------- lin1 (A resident) -> relu -> resident --------
    zero();
    ldgBw(w1, 0);
    stsB(0);
    __syncthreads();
    for(int c=0;c<8;c++){
        if(c+1<8) ldgBw(w1, (c+1)*32);
        comp(smb+RES + c*64, RSTR, smb+B_DB(c&1));
        if(c+1<8) stsB((c+1)&1);
        __syncthreads();
    }
#pragma unroll
    for(int f=0;f<2;f++)
#pragma unroll
    for(int nf=0;nf<8;nf++){
        int colb=wn*64+nf*8+2*tg;
        float2 bb=*(const float2*)(b1+colb);
#pragma unroll
        for(int h=0;h<2;h++){
            int rl=wm*32+f*16+h*8+gp;
            float ox=fmaxf(acc[f][nf][2*h]+bb.x,0.f);
            float oy=fmaxf(acc[f][nf][2*h+1]+bb.y,0.f);
            *(__half2*)(smc+RES + rl*RSTR + colb*2)=__floats2half2_rn(ox,oy);
        }
    }
    __syncthreads();

    // -------- lin2 (A resident) + resid(g_fea1) + LN + write fout --------
    zero();
    ldgBw(w2, 0);
    stsB(0);
    __syncthreads();
    for(int c=0;c<8;c++){
        if(c+1<8) ldgBw(w2, (c+1)*32);
        comp(smb+RES + c*64, RSTR, smb+B_DB(c&1));
        if(c+1<8) stsB((c+1)&1);
        __syncthreads();
    }
#pragma unroll
    for(int f=0;f<2;f++)
#pragma unroll
    for(int nf=0;nf<8;nf++){
        int colb=wn*64+nf*8+2*tg;
        float2 bb=*(const float2*)(b2v+colb);
#pragma unroll
        for(int h=0;h<2;h++){
            int row=row0+wm*32+f*16+h*8+gp;
            float2 rr=*(const float2*)(g_fea1+(size_t)row*256+colb);
            acc[f][nf][2*h+0]+=bb.x+rr.x;
            acc[f][nf][2*h+1]+=bb.y+rr.y;
        }
    }
    {
        float2* red=(float2*)smc;
#pragma unroll
        for(int f=0;f<2;f++)
#pragma unroll
        for(int h=0;h<2;h++){
            float su=0.f,sq=0.f;
#pragma unroll
            for(int nf=0;nf<8;nf++){
                float vx=acc[f][nf][2*h], vy=acc[f][nf][2*h+1];
                su+=vx+vy; sq+=vx*vx+vy*vy;
            }
            su+=__shfl_xor_sync(0xffffffffu,su,1); sq+=__shfl_xor_sync(0xffffffffu,sq,1);
            su+=__shfl_xor_sync(0xffffffffu,su,2); sq+=__shfl_xor_sync(0xffffffffu,sq,2);
            if(tg==0){ int rl=wm*32+f*16+h*8+gp; red[wn*128+rl]=make_float2(su,sq); }
        }
        __syncthreads();
#pragma unroll
        for(int f=0;f<2;f++)
#pragma unroll
        for(int h=0;h<2;h++){
            int rl=wm*32+f*16+h*8+gp;
            float S=0.f,Q=0.f;
#pragma unroll
            for(int w4=0;w4<4;w4++){ float2 v=red[w4*128+rl]; S+=v.x; Q+=v.y; }
            float m=S*(1.f/256.f), rs=rsqrtf(Q*(1.f/256.f)-m*m+1e-5f);
            int row=row0+rl;
#pragma unroll
            for(int nf=0;nf<8;nf++){
                int colb=wn*64+nf*8+2*tg;
                float2 g2=*(const float2*)(nfg+colb), bb2=*(const float2*)(nfb+colb);
                float ox=(acc[f][nf][2*h]-m)*rs*g2.x+bb2.x;
                float oy=(acc[f][nf][2*h+1]-m)*rs*g2.y+bb2.y;
                *(float2*)(fout+(size_t)row*256+colb)=make_float2(ox,oy);
            }
        }
    }
}

// ---------------- attention ----------------
__global__ __launch_bounds__(256) void k_attn(int s, const int* __restrict__ words) {
    if (__ldg(words + s) == 0) return;
    __shared__ float ks[16*257];
    __shared__ float vs[16*257];
    __shared__ float sc[512];
    int p = blockIdx.x, tid = threadIdx.x;
    for (int idx=tid; idx<16*256; idx+=256) {
        int m = idx >> 8, c = idx & 255;
        ks[m*257+c] = g_kh[((size_t)(m*PP + p))*VD + c];
        vs[m*257+c] = g_vv[((size_t)(m*PP + p))*VD + c];
    }
    __syncthreads();
    const float scale = 0.08838834764831845f;
#pragma unroll
    for (int rep=0; rep<2; rep++) {
        int si = tid + rep*256;
        int h = si >> 8, l = (si >> 4) & 15, m = si & 15;
        const float* qp = g_qh + ((size_t)(s*NB + l))*VD + h*DHD;
        const float* kp = ks + m*257 + h*DHD;
        float d = 0.f;
#pragma unroll 8
        for (int k=0;k<DHD;k++) d += qp[k]*kp[k];
        sc[si] = d*scale;
    }
    __syncthreads();
    if (tid < 32) {
        float* r = sc + tid*16;
        float mx = r[0];
#pragma unroll
        for (int m=1;m<16;m++) mx = fmaxf(mx, r[m]);
        float su=0.f;
#pragma unroll
        for (int m=0;m<16;m++){ float e = __expf(r[m]-mx); r[m]=e; su+=e; }
        float inv = 1.f/su;
#pragma unroll
        for (int m=0;m<16;m++) r[m]*=inv;
    }
    __syncthreads();
    for (int idx=tid; idx<4096; idx+=256) {
        int l = idx >> 8, c = idx & 255;
        int h = c >> 7;
        const float* a = sc + (h*16+l)*16;
        float accv = 0.f;
#pragma unroll
        for (int m=0;m<16;m++) accv += a[m]*vs[m*257+c];
        g_o[((size_t)(l*PP+p))*VD + c] = accv;
    }
}

// ---------------- launch ----------------
extern "C" void kernel_launch(void* const* d_in, const int* in_sizes, int n_in,
                              void* d_out, int out_size) {
    const float* hn         = (const float*)d_in[1];
    const float* feature    = (const float*)d_in[2];
    const float* embedding  = (const float*)d_in[3];
    const int*   words      = (const int*)  d_in[4];
    const float* qconv_w    = (const float*)d_in[5];
    const float* qconv_b    = (const float*)d_in[6];
    const float* mconv_w    = (const float*)d_in[7];
    const float* mnorm_g    = (const float*)d_in[8];
    const float* mnorm_b    = (const float*)d_in[9];
    const float* in_proj_w  = (const float*)d_in[10];
    const float* in_proj_b  = (const float*)d_in[11];
    const float* out_proj_w = (const float*)d_in[12];
    const float* out_proj_b = (const float*)d_in[13];
    const float* norm_g     = (const float*)d_in[14];
    const float* norm_b     = (const float*)d_in[15];
    const float* lin1_w     = (const float*)d_in[16];
    const float* lin1_b     = (const float*)d_in[17];
    const float* lin2_w     = (const float*)d_in[18];
    const float* lin2_b     = (const float*)d_in[19];
    const float* normf_g    = (const float*)d_in[20];
    const float* normf_b    = (const float*)d_in[21];

    cudaFuncSetAttribute(k_convkv, cudaFuncAttributeMaxDynamicSharedMemorySize, SMEM_BYTES);
    cudaFuncSetAttribute(k_mlp,    cudaFuncAttributeMaxDynamicSharedMemorySize, SMEM_BYTES);

    float *fA, *fB;
    cudaGetSymbolAddress((void**)&fA, g_featA);
    cudaGetSymbolAddress((void**)&fB, g_featB);

    // one-time precompute
    k_wsum9   <<<(9*HND*VD+255)/256, 256>>>(mconv_w);
    k_spbase  <<<(PP*VD+255)/256,    256>>>(mconv_w);
    k_hncon   <<<(NB*9*VD+255)/256,  256>>>(hn);
    k_assemble<<<(NB*PP*VD/4+255)/256, 256>>>();
    k_qh      <<<dim3(NB,SEQN), 256>>>(embedding, qconv_w, qconv_b, in_proj_w, in_proj_b);
    k_repack  <<<(9*VD*VD+255)/256,  256>>>(mconv_w);
    k_tr_in   <<<dim3(32,8,NB), 256>>>(feature, fA);

    for (int s=0; s<SEQN; s++) {
        const float* fin = (s&1) ? fB : fA;
        float* fout      = (s&1) ? fA : fB;
        k_convkv<<<128,512,SMEM_BYTES>>>(fin, mnorm_g, mnorm_b, in_proj_w, in_proj_b, words, s);
        k_attn  <<<PP,256>>>(s, words);
        k_mlp   <<<128,512,SMEM_BYTES>>>(out_proj_w, out_proj_b, norm_g, norm_b,
                                         lin1_w, lin1_b, lin2_w, lin2_b,
                                         normf_g, normf_b, words, s, fin, fout);
    }
    k_tr_out<<<dim3(32,8,NB), 256>>>(fA, (float*)d_out);
}

// round 12
// speedup vs baseline: 1.3532x; 1.3532x over previous
#include <cuda_runtime.h>
#include <cuda_fp16.h>
#include <math.h>
#include <stdint.h>

#define NB   16
#define SEQN 20
#define PP   1024
#define VD   256
#define HND  512
#define EMBD 300
#define CIN  776
#define DHD  128

#define OFF_A0  0
#define OFF_A1  10240
#define OFF_B0  20480
#define OFF_B1  40960
#define SMEM_BYTES 61440

// ---------------- scratch (device globals; no allocation) ----------------
__device__ float g_base [NB*PP*VD];
__device__ float g_t    [NB*PP*VD];
__device__ float g_kh   [NB*PP*VD];
__device__ float g_vv   [NB*PP*VD];
__device__ float g_o    [NB*PP*VD];
__device__ float g_fea1 [NB*PP*VD];
__device__ float g_featA[NB*PP*VD];   // NHWC ping
__device__ float g_featB[NB*PP*VD];   // NHWC pong
__device__ float g_wsum9[9*HND*VD];
__device__ float g_hncon[NB*9*VD];
__device__ float g_spbase[PP*VD];
__device__ float g_qh   [SEQN*NB*VD];
__device__ float g_wr   [9*VD*VD];    // [tap][oc][ic]

// ---------------- helpers ----------------
__device__ __forceinline__ uint32_t h2u(__half2 h){ return *(uint32_t*)&h; }
__device__ __forceinline__ void mma16(float* d, const uint32_t* a, const uint32_t* b){
    asm volatile("mma.sync.aligned.m16n8k16.row.col.f32.f16.f16.f32 "
        "{%0,%1,%2,%3}, {%4,%5,%6,%7}, {%8,%9}, {%0,%1,%2,%3};"
        : "+f"(d[0]), "+f"(d[1]), "+f"(d[2]), "+f"(d[3])
        : "r"(a[0]), "r"(a[1]), "r"(a[2]), "r"(a[3]), "r"(b[0]), "r"(b[1]));
}
__device__ __forceinline__ void ldsm4(uint32_t* r, uint32_t addr){
    asm volatile("ldmatrix.sync.aligned.m8n8.x4.shared.b16 {%0,%1,%2,%3}, [%4];"
        : "=r"(r[0]), "=r"(r[1]), "=r"(r[2]), "=r"(r[3]) : "r"(addr));
}

// ---------------- precompute kernels (validated) ----------------
__global__ void k_wsum9(const float* __restrict__ w) {
    int idx = blockIdx.x*256 + threadIdx.x;
    if (idx >= 9*HND*VD) return;
    int o = idx & 255, i = (idx >> 8) & 511, t = idx >> 17;
    int ty = t/3, tx = t%3;
    int kh0 = (ty==0)?1:0, kh1 = (ty==2)?1:2;
    int kw0 = (tx==0)?1:0, kw1 = (tx==2)?1:2;
    const float* wb = w + ((size_t)o*CIN + 264 + i)*9;
    float s = 0.f;
    for (int kh=kh0; kh<=kh1; kh++)
        for (int kw=kw0; kw<=kw1; kw++)
            s += wb[kh*3+kw];
    g_wsum9[idx] = s;
}

__global__ void k_hncon(const float* __restrict__ hn) {
    int idx = blockIdx.x*256 + threadIdx.x;
    if (idx >= NB*9*VD) return;
    int o = idx & 255, t = (idx >> 8) % 9, n = idx / (9*256);
    const float* hp = hn + (size_t)n*HND;
    const float* wp = g_wsum9 + (size_t)t*HND*VD + o;
    float s = 0.f;
    for (int i=0;i<HND;i++) s += hp[i]*wp[(size_t)i*VD];
    g_hncon[idx] = s;
}

__global__ void k_spbase(const float* __restrict__ w) {
    int idx = blockIdx.x*256 + threadIdx.x;
    if (idx >= PP*VD) return;
    int o = idx & 255, p = idx >> 8;
    int hh = p >> 5, ww = p & 31;
    float s = 0.f;
    for (int kh=0;kh<3;kh++) {
        int gh = hh+kh-1; if ((unsigned)gh >= 32u) continue;
        for (int kw=0;kw<3;kw++) {
            int gw = ww+kw-1; if ((unsigned)gw >= 32u) continue;
            float xmin = gw*0.0625f - 1.f, ymin = gh*0.0625f - 1.f;
            float xmax = xmin + 0.0625f,  ymax = ymin + 0.0625f;
            const float* wb = w + ((size_t)o*CIN + 256)*9 + kh*3+kw;
            s += xmin*wb[0] + ymin*wb[9] + xmax*wb[18] + ymax*wb[27]
               + 0.5f*(xmin+xmax)*wb[36] + 0.5f*(ymin+ymax)*wb[45]
               + 0.03125f*wb[54] + 0.03125f*wb[63];
        }
    }
    g_spbase[idx] = s;
}

__global__ void k_assemble() {
    int idx = blockIdx.x*256 + threadIdx.x;
    if (idx >= NB*PP*VD/4) return;
    int e = idx*4;
    int o = e & 255, p = (e >> 8) & 1023, n = e >> 18;
    int hh = p >> 5, ww = p & 31;
    int ty = (hh==0)?0:((hh==31)?2:1);
    int tx = (ww==0)?0:((ww==31)?2:1);
    float4 sp = *(const float4*)(g_spbase + (size_t)p*VD + o);
    float4 hc = *(const float4*)(g_hncon + ((size_t)(n*9 + ty*3+tx))*VD + o);
    float4 r; r.x=sp.x+hc.x; r.y=sp.y+hc.y; r.z=sp.z+hc.z; r.w=sp.w+hc.w;
    *(float4*)(g_base + (size_t)e) = r;
}

__global__ __launch_bounds__(256) void k_qh(const float* __restrict__ emb,
                                            const float* __restrict__ qw, const float* __restrict__ qb,
                                            const float* __restrict__ Wq, const float* __restrict__ bq) {
    __shared__ float es[304];
    __shared__ float qs[256];
    int n = blockIdx.x, s = blockIdx.y, c = threadIdx.x;
    for (int i=c; i<EMBD; i+=256) es[i] = emb[((size_t)n*SEQN+s)*EMBD + i];
    __syncthreads();
    float a = qb[c];
    const float* wr = qw + (size_t)c*EMBD;
    for (int e=0;e<EMBD;e++) a += es[e]*wr[e];
    qs[c] = fmaxf(a, 0.f);
    __syncthreads();
    float a2 = bq[c];
    const float* wr2 = Wq + (size_t)c*VD;
    for (int k=0;k<VD;k++) a2 += qs[k]*wr2[k];
    g_qh[((size_t)s*NB+n)*VD + c] = a2;
}

__global__ void k_repack(const float* __restrict__ w){
    int idx = blockIdx.x*256 + threadIdx.x;
    if (idx >= 9*VD*VD) return;
    int i = idx & 255, o = (idx >> 8) & 255, t = idx >> 16;
    g_wr[idx] = w[((size_t)o*CIN + i)*9 + t];
}

// ---------------- transposes (once each) ----------------
__global__ __launch_bounds__(256) void k_tr_in(const float* __restrict__ src, float* __restrict__ dst){
    __shared__ float t[32][33];
    int n = blockIdx.z, c0 = blockIdx.y*32, p0 = blockIdx.x*32;
    int i = threadIdx.x >> 5, j = threadIdx.x & 31;
    for (int r=0;r<32;r+=8)
        t[i+r][j] = src[((size_t)n*VD + c0+i+r)*PP + p0 + j];
    __syncthreads();
    for (int r=0;r<32;r+=8)
        dst[((size_t)n*PP + p0+i+r)*VD + c0 + j] = t[j][i+r];
}
__global__ __launch_bounds__(256) void k_tr_out(const float* __restrict__ src, float* __restrict__ dst){
    __shared__ float t[32][33];
    int n = blockIdx.z, c0 = blockIdx.y*32, p0 = blockIdx.x*32;
    int i = threadIdx.x >> 5, j = threadIdx.x & 31;
    for (int r=0;r<32;r+=8)
        t[i+r][j] = src[((size_t)n*PP + p0+i+r)*VD + c0 + j];
    __syncthreads();
    for (int r=0;r<32;r+=8)
        dst[((size_t)n*VD + c0+i+r)*PP + p0 + j] = t[j][i+r];
}

// ---------------- fp16 HMMA GEMM (R8, validated) ----------------
template<int MODE, int EPI>
__global__ __launch_bounds__(512, 1) void k_tc(const float* __restrict__ A, const float* __restrict__ W,
    const float* __restrict__ bias, const float* __restrict__ resid,
    const float* __restrict__ lng, const float* __restrict__ lnb,
    const int* __restrict__ words, int s, const float* __restrict__ fcur,
    float* __restrict__ C,
    const float* __restrict__ W2, const float* __restrict__ bias2, float* __restrict__ C2)
{
    extern __shared__ char smc[];
    const int tid  = threadIdx.x;
    const int lane = tid & 31;
    const int w    = tid >> 5;
    const int wm   = w & 3, wn = w >> 2;
    const int tg   = lane & 3, gp = lane >> 2;
    const int row0 = blockIdx.x*128;
    const int n    = row0 >> 10;
    const int p0   = row0 & 1023;

    if (MODE == 0 && blockIdx.y == 1){ W = W2; bias = bias2; C = C2; }

    if (EPI == 3){
        if (__ldg(words + s) == 0){
#pragma unroll
            for (int i=0;i<16;i++){
                int q = tid + i*512;
                size_t off = (size_t)(row0 + (q>>6))*256 + (q&63)*4;
                *(float4*)(C + off) = *(const float4*)(fcur + off);
            }
            return;
        }
    }

    float acc[2][8][4];
#pragma unroll
    for (int f=0;f<2;f++)
#pragma unroll
        for (int nf=0;nf<8;nf++)
#pragma unroll
            for (int j=0;j<4;j++) acc[f][nf][j] = 0.f;

    const int CH = MODE ? 72 : 8;
    const uint32_t smb = (uint32_t)__cvta_generic_to_shared(smc);
    const uint32_t rAoff = (uint32_t)((wm*32 + (lane&7) + ((lane>>3)&1)*8)*80 + ((lane>>4)&1)*16);
    const uint32_t rBoff = (uint32_t)((wn*64 + ((lane>>4)&1)*8 + (lane&7))*80 + ((lane>>3)&1)*16);

    auto ldgA = [&](int c, float4* r){
#pragma unroll
        for (int i=0;i<2;i++){
            int q = tid + i*512;
            int row = q>>3, c4 = q&7;
            if (MODE == 0){
                r[i] = *(const float4*)(A + (size_t)(row0+row)*256 + c*32 + c4*4);
            } else {
                int tap = c >> 3, kb = c & 7;
                int dh = tap/3 - 1, dw = tap%3 - 1;
                int p = p0 + row;
                int sh = (p>>5) + dh, sw = (p&31) + dw;
                float4 v = make_float4(0.f,0.f,0.f,0.f);
                if ((unsigned)sh < 32u && (unsigned)sw < 32u)
                    v = *(const float4*)(A + ((size_t)((n<<10) + (sh<<5) + sw))*256 + kb*32 + c4*4);
                r[i] = v;
            }
        }
    };
    auto ldgB = [&](int c, float4* r){
        const float* Wb; int k0;
        if (MODE == 0){ Wb = W; k0 = c*32; }
        else { Wb = g_wr + (size_t)(c>>3)*VD*VD; k0 = (c&7)*32; }
#pragma unroll
        for (int i=0;i<4;i++){
            int q = tid + i*512;
            r[i] = *(const float4*)(Wb + (size_t)(q>>3)*256 + k0 + (q&7)*4);
        }
    };
    auto stsA = [&](int buf, const float4* r){
        char* As = smc + (buf ? OFF_A1 : OFF_A0);
#pragma unroll
        for (int i=0;i<2;i++){
            int q = tid + i*512;
            __half2 h0 = __floats2half2_rn(r[i].x, r[i].y);
            __half2 h1 = __floats2half2_rn(r[i].z, r[i].w);
            *(uint2*)(As + (q>>3)*80 + (q&7)*8) = make_uint2(h2u(h0), h2u(h1));
        }
    };
    auto stsB = [&](int buf, const float4* r){
        char* Bs = smc + (buf ? OFF_B1 : OFF_B0);
#pragma unroll
        for (int i=0;i<4;i++){
            int q = tid + i*512;
            __half2 h0 = __floats2half2_rn(r[i].x, r[i].y);
            __half2 h1 = __floats2half2_rn(r[i].z, r[i].w);
            *(uint2*)(Bs + (q>>3)*80 + (q&7)*8) = make_uint2(h2u(h0), h2u(h1));
        }
    };
    auto compute = [&](int buf){
        uint32_t As = smb + (buf ? OFF_A1 : OFF_A0);
        uint32_t Bs = smb + (buf ? OFF_B1 : OFF_B0);
#pragma unroll
        for (int kk=0; kk<2; kk++){
            uint32_t a0[4], a1[4];
            ldsm4(a0, As + rAoff + kk*32);
            ldsm4(a1, As + rAoff + 16*80 + kk*32);
#pragma unroll
            for (int nfp=0; nfp<4; nfp++){
                uint32_t b4[4];
                ldsm4(b4, Bs + rBoff + nfp*16*80 + kk*32);
                mma16(acc[0][2*nfp+0], a0, &b4[0]);
                mma16(acc[1][2*nfp+0], a1, &b4[0]);
                mma16(acc[0][2*nfp+1], a0, &b4[2]);
                mma16(acc[1][2*nfp+1], a1, &b4[2]);
            }
        }
    };

    {
        float4 ra[2], rb[4];
        ldgA(0, ra); ldgB(0, rb);
        stsA(0, ra); stsB(0, rb);
    }
    __syncthreads();
    for (int c=0; c<CH; c++){
        float4 ra[2], rb[4];
        if (c+1 < CH){ ldgA(c+1, ra); ldgB(c+1, rb); }
        compute(c&1);
        if (c+1 < CH){ stsA((c+1)&1, ra); stsB((c+1)&1, rb); }
        __syncthreads();
    }

    if (EPI <= 1){
#pragma unroll
        for (int f=0;f<2;f++)
#pragma unroll
        for (int nf=0;nf<8;nf++){
            int colb = wn*64 + nf*8 + 2*tg;
            float2 bb = *(const float2*)(bias + colb);
#pragma unroll
            for (int h=0;h<2;h++){
                int row = row0 + wm*32 + f*16 + h*8 + gp;
                float2 o;
                o.x = acc[f][nf][2*h+0] + bb.x;
                o.y = acc[f][nf][2*h+1] + bb.y;
                if (EPI == 1){ o.x = fmaxf(o.x,0.f); o.y = fmaxf(o.y,0.f); }
                *(float2*)(C + (size_t)row*256 + colb) = o;
            }
        }
        return;
    }

#pragma unroll
    for (int f=0;f<2;f++)
#pragma unroll
    for (int nf=0;nf<8;nf++){
        int colb = wn*64 + nf*8 + 2*tg;
        float2 bb = make_float2(0.f, 0.f);
        if (EPI != 4) bb = *(const float2*)(bias + colb);
#pragma unroll
        for (int h=0;h<2;h++){
            int row = row0 + wm*32 + f*16 + h*8 + gp;
            float2 rr = *(const float2*)(resid + (size_t)row*256 + colb);
            float vx = acc[f][nf][2*h+0] + bb.x + rr.x;
            float vy = acc[f][nf][2*h+1] + bb.y + rr.y;
            if (EPI == 4){ vx = fmaxf(vx, 0.f); vy = fmaxf(vy, 0.f); }
            acc[f][nf][2*h+0] = vx;
            acc[f][nf][2*h+1] = vy;
        }
    }
    float2* red = (float2*)smc;
#pragma unroll
    for (int f=0;f<2;f++)
#pragma unroll
    for (int h=0;h<2;h++){
        float su = 0.f, sq = 0.f;
#pragma unroll
        for (int nf=0;nf<8;nf++){
            float vx = acc[f][nf][2*h+0], vy = acc[f][nf][2*h+1];
            su += vx + vy;
            sq += vx*vx + vy*vy;
        }
        su += __shfl_xor_sync(0xffffffffu, su, 1);
        sq += __shfl_xor_sync(0xffffffffu, sq, 1);
        su += __shfl_xor_sync(0xffffffffu, su, 2);
        sq += __shfl_xor_sync(0xffffffffu, sq, 2);
        if (tg == 0){
            int rloc = wm*32 + f*16 + h*8 + gp;
            red[wn*128 + rloc] = make_float2(su, sq);
        }
    }
    __syncthreads();
#pragma unroll
    for (int f=0;f<2;f++)
#pragma unroll
    for (int h=0;h<2;h++){
        int rloc = wm*32 + f*16 + h*8 + gp;
        float S = 0.f, Q = 0.f;
#pragma unroll
        for (int w4=0;w4<4;w4++){
            float2 v = red[w4*128 + rloc];
            S += v.x; Q += v.y;
        }
        float m  = S*(1.f/256.f);
        float rs = rsqrtf(Q*(1.f/256.f) - m*m + 1e-5f);
        int row = row0 + rloc;
#pragma unroll
        for (int nf=0;nf<8;nf++){
            int colb = wn*64 + nf*8 + 2*tg;
            float2 g2 = *(const float2*)(lng + colb);
            float2 b2 = *(const float2*)(lnb + colb);
            float2 o;
            o.x = (acc[f][nf][2*h+0]-m)*rs*g2.x + b2.x;
            o.y = (acc[f][nf][2*h+1]-m)*rs*g2.y + b2.y;
            *(float2*)(C + (size_t)row*256 + colb) = o;
        }
    }
}

// ---------------- attention (vectorized float4) ----------------
#define KPAD 260
__global__ __launch_bounds__(256) void k_attn(int s) {
    __shared__ float ks[16*KPAD];
    __shared__ float vs[16*KPAD];
    __shared__ float sc[512];
    int p = blockIdx.x, tid = threadIdx.x;
    // load kh/vv tiles: 16 m x 64 float4 each
    for (int idx=tid; idx<16*64; idx+=256) {
        int m = idx >> 6, c4 = idx & 63;
        size_t ga = ((size_t)(m*PP + p))*VD + c4*4;
        *(float4*)(ks + m*KPAD + c4*4) = *(const float4*)(g_kh + ga);
        *(float4*)(vs + m*KPAD + c4*4) = *(const float4*)(g_vv + ga);
    }
    __syncthreads();
    const float scale = 0.08838834764831845f;
#pragma unroll
    for (int rep=0; rep<2; rep++) {
        int si = tid + rep*256;
        int h = si >> 8, l = (si >> 4) & 15, m = si & 15;
        const float4* qp = (const float4*)(g_qh + ((size_t)(s*NB + l))*VD + h*DHD);
        const float4* kp = (const float4*)(ks + m*KPAD + h*DHD);
        float d = 0.f;
#pragma unroll
        for (int k=0;k<32;k++){
            float4 q4 = qp[k], k4 = kp[k];
            d += q4.x*k4.x + q4.y*k4.y + q4.z*k4.z + q4.w*k4.w;
        }
        sc[si] = d*scale;
    }
    __syncthreads();
    if (tid < 32) {
        float* r = sc + tid*16;
        float mx = r[0];
#pragma unroll
        for (int m=1;m<16;m++) mx = fmaxf(mx, r[m]);
        float su=0.f;
#pragma unroll
        for (int m=0;m<16;m++){ float e = __expf(r[m]-mx); r[m]=e; su+=e; }
        float inv = 1.f/su;
#pragma unroll
        for (int m=0;m<16;m++) r[m]*=inv;
    }
    __syncthreads();
    // o = attn @ vv : 16 l x 64 float4
    for (int idx=tid; idx<1024; idx+=256) {
        int l = idx >> 6, c4 = idx & 63;
        int h = c4 >> 5;
        const float* a = sc + (h*16+l)*16;
        float4 o4 = make_float4(0.f,0.f,0.f,0.f);
#pragma unroll
        for (int m=0;m<16;m++){
            float am = a[m];
            float4 v4 = *(const float4*)(vs + m*KPAD + c4*4);
            o4.x += am*v4.x; o4.y += am*v4.y; o4.z += am*v4.z; o4.w += am*v4.w;
        }
        *(float4*)(g_o + ((size_t)(l*PP+p))*VD + c4*4) = o4;
    }
}

// ---------------- launch ----------------
extern "C" void kernel_launch(void* const* d_in, const int* in_sizes, int n_in,
                              void* d_out, int out_size) {
    const float* hn         = (const float*)d_in[1];
    const float* feature    = (const float*)d_in[2];
    const float* embedding  = (const float*)d_in[3];
    const int*   words      = (const int*)  d_in[4];
    const float* qconv_w    = (const float*)d_in[5];
    const float* qconv_b    = (const float*)d_in[6];
    const float* mconv_w    = (const float*)d_in[7];
    const float* mnorm_g    = (const float*)d_in[8];
    const float* mnorm_b    = (const float*)d_in[9];
    const float* in_proj_w  = (const float*)d_in[10];
    const float* in_proj_b  = (const float*)d_in[11];
    const float* out_proj_w = (const float*)d_in[12];
    const float* out_proj_b = (const float*)d_in[13];
    const float* norm_g     = (const float*)d_in[14];
    const float* norm_b     = (const float*)d_in[15];
    const float* lin1_w     = (const float*)d_in[16];
    const float* lin1_b     = (const float*)d_in[17];
    const float* lin2_w     = (const float*)d_in[18];
    const float* lin2_b     = (const float*)d_in[19];
    const float* normf_g    = (const float*)d_in[20];
    const float* normf_b    = (const float*)d_in[21];

    cudaFuncSetAttribute(k_tc<0,0>, cudaFuncAttributeMaxDynamicSharedMemorySize, SMEM_BYTES);
    cudaFuncSetAttribute(k_tc<0,1>, cudaFuncAttributeMaxDynamicSharedMemorySize, SMEM_BYTES);
    cudaFuncSetAttribute(k_tc<0,2>, cudaFuncAttributeMaxDynamicSharedMemorySize, SMEM_BYTES);
    cudaFuncSetAttribute(k_tc<0,3>, cudaFuncAttributeMaxDynamicSharedMemorySize, SMEM_BYTES);
    cudaFuncSetAttribute(k_tc<1,4>, cudaFuncAttributeMaxDynamicSharedMemorySize, SMEM_BYTES);

    float *fA, *fB, *p_t, *p_kh, *p_vv, *p_o, *p_fea1, *p_base;
    cudaGetSymbolAddress((void**)&fA,     g_featA);
    cudaGetSymbolAddress((void**)&fB,     g_featB);
    cudaGetSymbolAddress((void**)&p_t,    g_t);
    cudaGetSymbolAddress((void**)&p_kh,   g_kh);
    cudaGetSymbolAddress((void**)&p_vv,   g_vv);
    cudaGetSymbolAddress((void**)&p_o,    g_o);
    cudaGetSymbolAddress((void**)&p_fea1, g_fea1);
    cudaGetSymbolAddress((void**)&p_base, g_base);

    // one-time precompute
    k_wsum9   <<<(9*HND*VD+255)/256, 256>>>(mconv_w);
    k_spbase  <<<(PP*VD+255)/256,    256>>>(mconv_w);
    k_hncon   <<<(NB*9*VD+255)/256,  256>>>(hn);
    k_assemble<<<(NB*PP*VD/4+255)/256, 256>>>();
    k_qh      <<<dim3(NB,SEQN), 256>>>(embedding, qconv_w, qconv_b, in_proj_w, in_proj_b);
    k_repack  <<<(9*VD*VD+255)/256,  256>>>(mconv_w);
    k_tr_in   <<<dim3(32,8,NB), 256>>>(feature, fA);

    for (int s=0; s<SEQN; s++) {
        const float* fin = (s&1) ? fB : fA;
        float* fout      = (s&1) ? fA : fB;

        k_tc<1,4><<<128,512,SMEM_BYTES>>>(fin, nullptr, nullptr, p_base,
                                          mnorm_g, mnorm_b, nullptr, 0, nullptr, p_t,
                                          nullptr, nullptr, nullptr);
        k_tc<0,0><<<dim3(128,2),512,SMEM_BYTES>>>(p_t, in_proj_w + VD*VD, in_proj_b + VD,
                                          nullptr, nullptr, nullptr, nullptr, 0, nullptr, p_kh,
                                          in_proj_w + 2*VD*VD, in_proj_b + 2*VD, p_vv);
        k_attn <<<PP,256>>>(s);
        k_tc<0,2><<<128,512,SMEM_BYTES>>>(p_o, out_proj_w, out_proj_b,
                                          p_t, norm_g, norm_b, nullptr, 0, nullptr, p_fea1,
                                          nullptr, nullptr, nullptr);
        k_tc<0,1><<<128,512,SMEM_BYTES>>>(p_fea1, lin1_w, lin1_b,
                                          nullptr, nullptr, nullptr, nullptr, 0, nullptr, p_kh,
                                          nullptr, nullptr, nullptr);
        k_tc<0,3><<<128,512,SMEM_BYTES>>>(p_kh, lin2_w, lin2_b,
                                          p_fea1, normf_g, normf_b, words, s, fin, fout,
                                          nullptr, nullptr, nullptr);
    }
    k_tr_out<<<dim3(32,8,NB), 256>>>(fA, (float*)d_out);
}

// round 15
// speedup vs baseline: 1.4727x; 1.0883x over previous
#include <cuda_runtime.h>
#include <cuda_fp16.h>
#include <math.h>
#include <stdint.h>

#define NB   16
#define SEQN 20
#define PP   1024
#define VD   256
#define HND  512
#define EMBD 300
#define CIN  776
#define DHD  128

// K-chunk 64. A tile 128x64 halves @144B stride, B tile 256x64 halves @144B stride, double buffered.
#define A_DB0   0
#define A_DB1   18432
#define B_DB0   36864
#define B_DB1   73728
#define SMEM_BYTES 110592

// ---------------- scratch (device globals; no allocation) ----------------
__device__ float  g_base [NB*PP*VD];
__device__ float  g_t    [NB*PP*VD];
__device__ float  g_kh   [NB*PP*VD];
__device__ float  g_vv   [NB*PP*VD];
__device__ float  g_o    [NB*PP*VD];
__device__ float  g_fea1 [NB*PP*VD];
__device__ float  g_featA[NB*PP*VD];   // NHWC ping
__device__ float  g_featB[NB*PP*VD];   // NHWC pong
__device__ float  g_wsum9[9*HND*VD];
__device__ float  g_hncon[NB*9*VD];
__device__ float  g_spbase[PP*VD];
__device__ float  g_qh   [SEQN*NB*VD];
__device__ __half g_wrh  [9*VD*VD];    // conv weights fp16: [tap][oc][ic]
__device__ __half g_wkh  [VD*VD];
__device__ __half g_wvh  [VD*VD];
__device__ __half g_woh  [VD*VD];
__device__ __half g_w1h  [VD*VD];
__device__ __half g_w2h  [VD*VD];

// ---------------- helpers ----------------
__device__ __forceinline__ uint32_t h2u(__half2 h){ return *(uint32_t*)&h; }
__device__ __forceinline__ void mma16(float* d, const uint32_t* a, const uint32_t* b){
    asm volatile("mma.sync.aligned.m16n8k16.row.col.f32.f16.f16.f32 "
        "{%0,%1,%2,%3}, {%4,%5,%6,%7}, {%8,%9}, {%0,%1,%2,%3};"
        : "+f"(d[0]), "+f"(d[1]), "+f"(d[2]), "+f"(d[3])
        : "r"(a[0]), "r"(a[1]), "r"(a[2]), "r"(a[3]), "r"(b[0]), "r"(b[1]));
}
__device__ __forceinline__ void ldsm4(uint32_t* r, uint32_t addr){
    asm volatile("ldmatrix.sync.aligned.m8n8.x4.shared.b16 {%0,%1,%2,%3}, [%4];"
        : "=r"(r[0]), "=r"(r[1]), "=r"(r[2]), "=r"(r[3]) : "r"(addr));
}

// ---------------- precompute kernels (validated) ----------------
__global__ void k_wsum9(const float* __restrict__ w) {
    int idx = blockIdx.x*256 + threadIdx.x;
    if (idx >= 9*HND*VD) return;
    int o = idx & 255, i = (idx >> 8) & 511, t = idx >> 17;
    int ty = t/3, tx = t%3;
    int kh0 = (ty==0)?1:0, kh1 = (ty==2)?1:2;
    int kw0 = (tx==0)?1:0, kw1 = (tx==2)?1:2;
    const float* wb = w + ((size_t)o*CIN + 264 + i)*9;
    float s = 0.f;
    for (int kh=kh0; kh<=kh1; kh++)
        for (int kw=kw0; kw<=kw1; kw++)
            s += wb[kh*3+kw];
    g_wsum9[idx] = s;
}

__global__ void k_hncon(const float* __restrict__ hn) {
    int idx = blockIdx.x*256 + threadIdx.x;
    if (idx >= NB*9*VD) return;
    int o = idx & 255, t = (idx >> 8) % 9, n = idx / (9*256);
    const float* hp = hn + (size_t)n*HND;
    const float* wp = g_wsum9 + (size_t)t*HND*VD + o;
    float s = 0.f;
    for (int i=0;i<HND;i++) s += hp[i]*wp[(size_t)i*VD];
    g_hncon[idx] = s;
}

__global__ void k_spbase(const float* __restrict__ w) {
    int idx = blockIdx.x*256 + threadIdx.x;
    if (idx >= PP*VD) return;
    int o = idx & 255, p = idx >> 8;
    int hh = p >> 5, ww = p & 31;
    float s = 0.f;
    for (int kh=0;kh<3;kh++) {
        int gh = hh+kh-1; if ((unsigned)gh >= 32u) continue;
        for (int kw=0;kw<3;kw++) {
            int gw = ww+kw-1; if ((unsigned)gw >= 32u) continue;
            float xmin = gw*0.0625f - 1.f, ymin = gh*0.0625f - 1.f;
            float xmax = xmin + 0.0625f,  ymax = ymin + 0.0625f;
            const float* wb = w + ((size_t)o*CIN + 256)*9 + kh*3+kw;
            s += xmin*wb[0] + ymin*wb[9] + xmax*wb[18] + ymax*wb[27]
               + 0.5f*(xmin+xmax)*wb[36] + 0.5f*(ymin+ymax)*wb[45]
               + 0.03125f*wb[54] + 0.03125f*wb[63];
        }
    }
    g_spbase[idx] = s;
}

__global__ void k_assemble() {
    int idx = blockIdx.x*256 + threadIdx.x;
    if (idx >= NB*PP*VD/4) return;
    int e = idx*4;
    int o = e & 255, p = (e >> 8) & 1023, n = e >> 18;
    int hh = p >> 5, ww = p & 31;
    int ty = (hh==0)?0:((hh==31)?2:1);
    int tx = (ww==0)?0:((ww==31)?2:1);
    float4 sp = *(const float4*)(g_spbase + (size_t)p*VD + o);
    float4 hc = *(const float4*)(g_hncon + ((size_t)(n*9 + ty*3+tx))*VD + o);
    float4 r; r.x=sp.x+hc.x; r.y=sp.y+hc.y; r.z=sp.z+hc.z; r.w=sp.w+hc.w;
    *(float4*)(g_base + (size_t)e) = r;
}

__global__ __launch_bounds__(256) void k_qh(const float* __restrict__ emb,
                                            const float* __restrict__ qw, const float* __restrict__ qb,
                                            const float* __restrict__ Wq, const float* __restrict__ bq) {
    __shared__ float es[304];
    __shared__ float qs[256];
    int n = blockIdx.x, s = blockIdx.y, c = threadIdx.x;
    for (int i=c; i<EMBD; i+=256) es[i] = emb[((size_t)n*SEQN+s)*EMBD + i];
    __syncthreads();
    float a = qb[c];
    const float* wr = qw + (size_t)c*EMBD;
    for (int e=0;e<EMBD;e++) a += es[e]*wr[e];
    qs[c] = fmaxf(a, 0.f);
    __syncthreads();
    float a2 = bq[c];
    const float* wr2 = Wq + (size_t)c*VD;
    for (int k=0;k<VD;k++) a2 += qs[k]*wr2[k];
    g_qh[((size_t)s*NB+n)*VD + c] = a2;
}

__global__ void k_repack_h(const float* __restrict__ w){
    int idx = blockIdx.x*256 + threadIdx.x;
    if (idx >= 9*VD*VD) return;
    int i = idx & 255, o = (idx >> 8) & 255, t = idx >> 16;
    g_wrh[idx] = __float2half(w[((size_t)o*CIN + i)*9 + t]);
}

__global__ void k_half(const float* __restrict__ src, __half* __restrict__ dst, int n){
    int i = blockIdx.x*256 + threadIdx.x;
    if (2*i < n){
        float2 v = *(const float2*)(src + 2*i);
        *(__half2*)(dst + 2*i) = __floats2half2_rn(v.x, v.y);
    }
}

// ---------------- transposes (once each) ----------------
__global__ __launch_bounds__(256) void k_tr_in(const float* __restrict__ src, float* __restrict__ dst){
    __shared__ float t[32][33];
    int n = blockIdx.z, c0 = blockIdx.y*32, p0 = blockIdx.x*32;
    int i = threadIdx.x >> 5, j = threadIdx.x & 31;
    for (int r=0;r<32;r+=8)
        t[i+r][j] = src[((size_t)n*VD + c0+i+r)*PP + p0 + j];
    __syncthreads();
    for (int r=0;r<32;r+=8)
        dst[((size_t)n*PP + p0+i+r)*VD + c0 + j] = t[j][i+r];
}
__global__ __launch_bounds__(256) void k_tr_out(const float* __restrict__ src, float* __restrict__ dst){
    __shared__ float t[32][33];
    int n = blockIdx.z, c0 = blockIdx.y*32, p0 = blockIdx.x*32;
    int i = threadIdx.x >> 5, j = threadIdx.x & 31;
    for (int r=0;r<32;r+=8)
        t[i+r][j] = src[((size_t)n*PP + p0+i+r)*VD + c0 + j];
    __syncthreads();
    for (int r=0;r<32;r+=8)
        dst[((size_t)n*VD + c0+i+r)*PP + p0 + j] = t[j][i+r];
}

// ---------------- fp16 HMMA GEMM, K-chunk 64, fp16 weights ----------------
// MODE 0: plain GEMM, K=256 (grid.y=1 -> W2/bias2/C2).  MODE 1: conv 9-tap, W=g_wrh, resid=base.
// EPI 0:+bias  1:+bias,relu  2:+bias+resid,LN  3:EPI2+word-gate(early exit)  4:LN(relu(acc+resid))
template<int MODE, int EPI>
__global__ __launch_bounds__(512, 1) void k_tc(const float* __restrict__ A, const __half* __restrict__ W,
    const float* __restrict__ bias, const float* __restrict__ resid,
    const float* __restrict__ lng, const float* __restrict__ lnb,
    const int* __restrict__ words, int s, const float* __restrict__ fcur,
    float* __restrict__ C,
    const __half* __restrict__ W2, const float* __restrict__ bias2, float* __restrict__ C2)
{
    extern __shared__ char smc[];
    const int tid  = threadIdx.x;
    const int lane = tid & 31;
    const int w    = tid >> 5;
    const int wm   = w & 3, wn = w >> 2;
    const int tg   = lane & 3, gp = lane >> 2;
    const int row0 = blockIdx.x*128;
    const int n    = row0 >> 10;
    const int p0   = row0 & 1023;

    if (MODE == 0 && blockIdx.y == 1){ W = W2; bias = bias2; C = C2; }

    if (EPI == 3){
        if (__ldg(words + s) == 0){
#pragma unroll
            for (int i=0;i<16;i++){
                int q = tid + i*512;
                size_t off = (size_t)(row0 + (q>>6))*256 + (q&63)*4;
                *(float4*)(C + off) = *(const float4*)(fcur + off);
            }
            return;
        }
    }

    float acc[2][8][4];
#pragma unroll
    for (int f=0;f<2;f++)
#pragma unroll
        for (int nf=0;nf<8;nf++)
#pragma unroll
            for (int j=0;j<4;j++) acc[f][nf][j] = 0.f;

    const int CH = MODE ? 36 : 4;       // K-chunk 64
    const uint32_t smb = (uint32_t)__cvta_generic_to_shared(smc);
    const uint32_t rAoff = (uint32_t)((wm*32 + (lane&7) + ((lane>>3)&1)*8)*144 + ((lane>>4)&1)*16);
    const uint32_t rBoff = (uint32_t)((wn*64 + ((lane>>4)&1)*8 + (lane&7))*144 + ((lane>>3)&1)*16);

    auto ldgA = [&](int c, float4* r){
#pragma unroll
        for (int i=0;i<2;i++){
            int q = tid + i*512;          // 1024 slots: row=q>>3, c8=q&7 (8 halves each)
            int row = q>>3, c8 = q&7;
            if (MODE == 0){
                const float* base = A + (size_t)(row0+row)*256 + c*64 + c8*8;
                r[2*i]   = *(const float4*)(base);
                r[2*i+1] = *(const float4*)(base+4);
            } else {
                int tap = c >> 2, kb = c & 3;
                int dh = tap/3 - 1, dw = tap%3 - 1;
                int p = p0 + row;
                int sh = (p>>5) + dh, sw = (p&31) + dw;
                float4 v0 = make_float4(0.f,0.f,0.f,0.f), v1 = v0;
                if ((unsigned)sh < 32u && (unsigned)sw < 32u){
                    const float* base = A + ((size_t)((n<<10) + (sh<<5) + sw))*256 + kb*64 + c8*8;
                    v0 = *(const float4*)(base);
                    v1 = *(const float4*)(base+4);
                }
                r[2*i] = v0; r[2*i+1] = v1;
            }
        }
    };
    auto ldgB = [&](int c, uint4* r){
        const __half* Wb; int k0;
        if (MODE == 0){ Wb = W; k0 = c*64; }
        else { Wb = g_wrh + (size_t)(c>>2)*VD*VD; k0 = (c&3)*64; }
#pragma unroll
        for (int i=0;i<4;i++){
            int q = tid + i*512;          // 2048 slots: row=q>>3, c8=q&7
            r[i] = *(const uint4*)(Wb + (size_t)(q>>3)*256 + k0 + (q&7)*8);
        }
    };
    auto stsA = [&](int buf, const float4* r){
        char* As = smc + (buf ? A_DB1 : A_DB0);
#pragma unroll
        for (int i=0;i<2;i++){
            int q = tid + i*512;
            uint4 v;
            v.x = h2u(__floats2half2_rn(r[2*i].x,   r[2*i].y));
            v.y = h2u(__floats2half2_rn(r[2*i].z,   r[2*i].w));
            v.z = h2u(__floats2half2_rn(r[2*i+1].x, r[2*i+1].y));
            v.w = h2u(__floats2half2_rn(r[2*i+1].z, r[2*i+1].w));
            *(uint4*)(As + (q>>3)*144 + (q&7)*16) = v;
        }
    };
    auto stsB = [&](int buf, const uint4* r){
        char* Bs = smc + (buf ? B_DB1 : B_DB0);
#pragma unroll
        for (int i=0;i<4;i++){
            int q = tid + i*512;
            *(uint4*)(Bs + (q>>3)*144 + (q&7)*16) = r[i];
        }
    };
    auto compute = [&](int buf){
        uint32_t As = smb + (buf ? A_DB1 : A_DB0);
        uint32_t Bs = smb + (buf ? B_DB1 : B_DB0);
#pragma unroll
        for (int kk=0; kk<4; kk++){
            uint32_t a0[4], a1[4];
            ldsm4(a0, As + rAoff + kk*32);
            ldsm4(a1, As + rAoff + 16*144 + kk*32);
#pragma unroll
            for (int nfp=0; nfp<4; nfp++){
                uint32_t b4[4];
                ldsm4(b4, Bs + rBoff + nfp*16*144 + kk*32);
                mma16(acc[0][2*nfp+0], a0, &b4[0]);
                mma16(acc[1][2*nfp+0], a1, &b4[0]);
                mma16(acc[0][2*nfp+1], a0, &b4[2]);
                mma16(acc[1][2*nfp+1], a1, &b4[2]);
            }
        }
    };

    {
        float4 ra[4]; uint4 rb[4];
        ldgA(0, ra); ldgB(0, rb);
        stsA(0, ra); stsB(0, rb);
    }
    __syncthreads();
    for (int c=0; c<CH; c++){
        float4 ra[4]; uint4 rb[4];
        if (c+1 < CH){ ldgA(c+1, ra); ldgB(c+1, rb); }
        compute(c&1);
        if (c+1 < CH){ stsA((c+1)&1, ra); stsB((c+1)&1, rb); }
        __syncthreads();
    }

    // -------- epilogue (identical to R8/R12) --------
    if (EPI <= 1){
#pragma unroll
        for (int f=0;f<2;f++)
#pragma unroll
        for (int nf=0;nf<8;nf++){
            int colb = wn*64 + nf*8 + 2*tg;
            float2 bb = *(const float2*)(bias + colb);
#pragma unroll
            for (int h=0;h<2;h++){
                int row = row0 + wm*32 + f*16 + h*8 + gp;
                float2 o;
                o.x = acc[f][nf][2*h+0] + bb.x;
                o.y = acc[f][nf][2*h+1] + bb.y;
                if (EPI == 1){ o.x = fmaxf(o.x,0.f); o.y = fmaxf(o.y,0.f); }
                *(float2*)(C + (size_t)row*256 + colb) = o;
            }
        }
        return;
    }

#pragma unroll
    for (int f=0;f<2;f++)
#pragma unroll
    for (int nf=0;nf<8;nf++){
        int colb = wn*64 + nf*8 + 2*tg;
        float2 bb = make_float2(0.f, 0.f);
        if (EPI != 4) bb = *(const float2*)(bias + colb);
#pragma unroll
        for (int h=0;h<2;h++){
            int row = row0 + wm*32 + f*16 + h*8 + gp;
            float2 rr = *(const float2*)(resid + (size_t)row*256 + colb);
            float vx = acc[f][nf][2*h+0] + bb.x + rr.x;
            float vy = acc[f][nf][2*h+1] + bb.y + rr.y;
            if (EPI == 4){ vx = fmaxf(vx, 0.f); vy = fmaxf(vy, 0.f); }
            acc[f][nf][2*h+0] = vx;
            acc[f][nf][2*h+1] = vy;
        }
    }
    float2* red = (float2*)smc;
#pragma unroll
    for (int f=0;f<2;f++)
#pragma unroll
    for (int h=0;h<2;h++){
        float su = 0.f, sq = 0.f;
#pragma unroll
        for (int nf=0;nf<8;nf++){
            float vx = acc[f][nf][2*h+0], vy = acc[f][nf][2*h+1];
            su += vx + vy;
            sq += vx*vx + vy*vy;
        }
        su += __shfl_xor_sync(0xffffffffu, su, 1);
        sq += __shfl_xor_sync(0xffffffffu, sq, 1);
        su += __shfl_xor_sync(0xffffffffu, su, 2);
        sq += __shfl_xor_sync(0xffffffffu, sq, 2);
        if (tg == 0){
            int rloc = wm*32 + f*16 + h*8 + gp;
            red[wn*128 + rloc] = make_float2(su, sq);
        }
    }
    __syncthreads();
#pragma unroll
    for (int f=0;f<2;f++)
#pragma unroll
    for (int h=0;h<2;h++){
        int rloc = wm*32 + f*16 + h*8 + gp;
        float S = 0.f, Q = 0.f;
#pragma unroll
        for (int w4=0;w4<4;w4++){
            float2 v = red[w4*128 + rloc];
            S += v.x; Q += v.y;
        }
        float m  = S*(1.f/256.f);
        float rs = rsqrtf(Q*(1.f/256.f) - m*m + 1e-5f);
        int row = row0 + rloc;
#pragma unroll
        for (int nf=0;nf<8;nf++){
            int colb = wn*64 + nf*8 + 2*tg;
            float2 g2 = *(const float2*)(lng + colb);
            float2 b2 = *(const float2*)(lnb + colb);
            float2 o;
            o.x = (acc[f][nf][2*h+0]-m)*rs*g2.x + b2.x;
            o.y = (acc[f][nf][2*h+1]-m)*rs*g2.y + b2.y;
            *(float2*)(C + (size_t)row*256 + colb) = o;
        }
    }
}

// ---------------- attention (vectorized float4, validated R12) ----------------
#define KPAD 260
__global__ __launch_bounds__(256) void k_attn(int s) {
    __shared__ float ks[16*KPAD];
    __shared__ float vs[16*KPAD];
    __shared__ float sc[512];
    int p = blockIdx.x, tid = threadIdx.x;
    for (int idx=tid; idx<16*64; idx+=256) {
        int m = idx >> 6, c4 = idx & 63;
        size_t ga = ((size_t)(m*PP + p))*VD + c4*4;
        *(float4*)(ks + m*KPAD + c4*4) = *(const float4*)(g_kh + ga);
        *(float4*)(vs + m*KPAD + c4*4) = *(const float4*)(g_vv + ga);
    }
    __syncthreads();
    const float scale = 0.08838834764831845f;
#pragma unroll
    for (int rep=0; rep<2; rep++) {
        int si = tid + rep*256;
        int h = si >> 8, l = (si >> 4) & 15, m = si & 15;
        const float4* qp = (const float4*)(g_qh + ((size_t)(s*NB + l))*VD + h*DHD);
        const float4* kp = (const float4*)(ks + m*KPAD + h*DHD);
        float d = 0.f;
#pragma unroll
        for (int k=0;k<32;k++){
            float4 q4 = qp[k], k4 = kp[k];
            d += q4.x*k4.x + q4.y*k4.y + q4.z*k4.z + q4.w*k4.w;
        }
        sc[si] = d*scale;
    }
    __syncthreads();
    if (tid < 32) {
        float* r = sc + tid*16;
        float mx = r[0];
#pragma unroll
        for (int m=1;m<16;m++) mx = fmaxf(mx, r[m]);
        float su=0.f;
#pragma unroll
        for (int m=0;m<16;m++){ float e = __expf(r[m]-mx); r[m]=e; su+=e; }
        float inv = 1.f/su;
#pragma unroll
        for (int m=0;m<16;m++) r[m]*=inv;
    }
    __syncthreads();
    for (int idx=tid; idx<1024; idx+=256) {
        int l = idx >> 6, c4 = idx & 63;
        int h = c4 >> 5;
        const float* a = sc + (h*16+l)*16;
        float4 o4 = make_float4(0.f,0.f,0.f,0.f);
#pragma unroll
        for (int m=0;m<16;m++){
            float am = a[m];
            float4 v4 = *(const float4*)(vs + m*KPAD + c4*4);
            o4.x += am*v4.x; o4.y += am*v4.y; o4.z += am*v4.z; o4.w += am*v4.w;
        }
        *(float4*)(g_o + ((size_t)(l*PP+p))*VD + c4*4) = o4;
    }
}

// ---------------- launch ----------------
extern "C" void kernel_launch(void* const* d_in, const int* in_sizes, int n_in,
                              void* d_out, int out_size) {
    const float* hn         = (const float*)d_in[1];
    const float* feature    = (const float*)d_in[2];
    const float* embedding  = (const float*)d_in[3];
    const int*   words      = (const int*)  d_in[4];
    const float* qconv_w    = (const float*)d_in[5];
    const float* qconv_b    = (const float*)d_in[6];
    const float* mconv_w    = (const float*)d_in[7];
    const float* mnorm_g    = (const float*)d_in[8];
    const float* mnorm_b    = (const float*)d_in[9];
    const float* in_proj_w  = (const float*)d_in[10];
    const float* in_proj_b  = (const float*)d_in[11];
    const float* out_proj_w = (const float*)d_in[12];
    const float* out_proj_b = (const float*)d_in[13];
    const float* norm_g     = (const float*)d_in[14];
    const float* norm_b     = (const float*)d_in[15];
    const float* lin1_w     = (const float*)d_in[16];
    const float* lin1_b     = (const float*)d_in[17];
    const float* lin2_w     = (const float*)d_in[18];
    const float* lin2_b     = (const float*)d_in[19];
    const float* normf_g    = (const float*)d_in[20];
    const float* normf_b    = (const float*)d_in[21];

    cudaFuncSetAttribute(k_tc<0,0>, cudaFuncAttributeMaxDynamicSharedMemorySize, SMEM_BYTES);
    cudaFuncSetAttribute(k_tc<0,1>, cudaFuncAttributeMaxDynamicSharedMemorySize, SMEM_BYTES);
    cudaFuncSetAttribute(k_tc<0,2>, cudaFuncAttributeMaxDynamicSharedMemorySize, SMEM_BYTES);
    cudaFuncSetAttribute(k_tc<0,3>, cudaFuncAttributeMaxDynamicSharedMemorySize, SMEM_BYTES);
    cudaFuncSetAttribute(k_tc<1,4>, cudaFuncAttributeMaxDynamicSharedMemorySize, SMEM_BYTES);

    float *fA, *fB, *p_t, *p_kh, *p_vv, *p_o, *p_fea1, *p_base;
    __half *p_wkh, *p_wvh, *p_woh, *p_w1h, *p_w2h;
    cudaGetSymbolAddress((void**)&fA,     g_featA);
    cudaGetSymbolAddress((void**)&fB,     g_featB);
    cudaGetSymbolAddress((void**)&p_t,    g_t);
    cudaGetSymbolAddress((void**)&p_kh,   g_kh);
    cudaGetSymbolAddress((void**)&p_vv,   g_vv);
    cudaGetSymbolAddress((void**)&p_o,    g_o);
    cudaGetSymbolAddress((void**)&p_fea1, g_fea1);
    cudaGetSymbolAddress((void**)&p_base, g_base);
    cudaGetSymbolAddress((void**)&p_wkh,  g_wkh);
    cudaGetSymbolAddress((void**)&p_wvh,  g_wvh);
    cudaGetSymbolAddress((void**)&p_woh,  g_woh);
    cudaGetSymbolAddress((void**)&p_w1h,  g_w1h);
    cudaGetSymbolAddress((void**)&p_w2h,  g_w2h);

    // one-time precompute
    k_wsum9    <<<(9*HND*VD+255)/256, 256>>>(mconv_w);
    k_spbase   <<<(PP*VD+255)/256,    256>>>(mconv_w);
    k_hncon    <<<(NB*9*VD+255)/256,  256>>>(hn);
    k_assemble <<<(NB*PP*VD/4+255)/256, 256>>>();
    k_qh       <<<dim3(NB,SEQN), 256>>>(embedding, qconv_w, qconv_b, in_proj_w, in_proj_b);
    k_repack_h <<<(9*VD*VD+255)/256,  256>>>(mconv_w);
    k_half     <<<128,256>>>(in_proj_w + VD*VD,   p_wkh, VD*VD);
    k_half     <<<128,256>>>(in_proj_w + 2*VD*VD, p_wvh, VD*VD);
    k_half     <<<128,256>>>(out_proj_w,          p_woh, VD*VD);
    k_half     <<<128,256>>>(lin1_w,              p_w1h, VD*VD);
    k_half     <<<128,256>>>(lin2_w,              p_w2h, VD*VD);
    k_tr_in    <<<dim3(32,8,NB), 256>>>(feature, fA);

    for (int s=0; s<SEQN; s++) {
        const float* fin = (s&1) ? fB : fA;
        float* fout      = (s&1) ? fA : fB;

        k_tc<1,4><<<128,512,SMEM_BYTES>>>(fin, nullptr, nullptr, p_base,
                                          mnorm_g, mnorm_b, nullptr, 0, nullptr, p_t,
                                          nullptr, nullptr, nullptr);
        k_tc<0,0><<<dim3(128,2),512,SMEM_BYTES>>>(p_t, p_wkh, in_proj_b + VD,
                                          nullptr, nullptr, nullptr, nullptr, 0, nullptr, p_kh,
                                          p_wvh, in_proj_b + 2*VD, p_vv);
        k_attn <<<PP,256>>>(s);
        k_tc<0,2><<<128,512,SMEM_BYTES>>>(p_o, p_woh, out_proj_b,
                                          p_t, norm_g, norm_b, nullptr, 0, nullptr, p_fea1,
                                          nullptr, nullptr, nullptr);
        k_tc<0,1><<<128,512,SMEM_BYTES>>>(p_fea1, p_w1h, lin1_b,
                                          nullptr, nullptr, nullptr, nullptr, 0, nullptr, p_kh,
                                          nullptr, nullptr, nullptr);
        k_tc<0,3><<<128,512,SMEM_BYTES>>>(p_kh, p_w2h, lin2_b,
                                          p_fea1, normf_g, normf_b, words, s, fin, fout,
                                          nullptr, nullptr, nullptr);
    }
    k_tr_out<<<dim3(32,8,NB), 256>>>(fA, (float*)d_out);
}

// round 17
// speedup vs baseline: 1.5086x; 1.0244x over previous
#include <cuda_runtime.h>
#include <cuda_fp16.h>
#include <math.h>
#include <stdint.h>

#define NB   16
#define SEQN 20
#define PP   1024
#define VD   256
#define HND  512
#define EMBD 300
#define CIN  776
#define DHD  128

// k_tc smem: K-chunk 64. A 128x144B, B 256x144B, double buffered.
#define A_DB0   0
#define A_DB1   18432
#define B_DB0   36864
#define B_DB1   73728
#define SMEM_BYTES 110592

// k_kv smem: resident A 128x528B, B dbuf 2x256x144B
#define KV_B0   67584
#define KV_B1   104448
#define KV_SMEM 141312

// ---------------- scratch (device globals; no allocation) ----------------
__device__ float  g_base [NB*PP*VD];
__device__ float  g_t    [NB*PP*VD];
__device__ float  g_kh   [NB*PP*VD];
__device__ float  g_vv   [NB*PP*VD];
__device__ float  g_o    [NB*PP*VD];
__device__ float  g_fea1 [NB*PP*VD];
__device__ float  g_featA[NB*PP*VD];   // NHWC ping
__device__ float  g_featB[NB*PP*VD];   // NHWC pong
__device__ float  g_wsum9[9*HND*VD];
__device__ float  g_hncon[NB*9*VD];
__device__ float  g_spbase[PP*VD];
__device__ float  g_qh   [SEQN*NB*VD];
__device__ __half g_wrh  [9*VD*VD];    // conv weights fp16: [tap][oc][ic]
__device__ __half g_wkh  [VD*VD];
__device__ __half g_wvh  [VD*VD];
__device__ __half g_woh  [VD*VD];
__device__ __half g_w1h  [VD*VD];
__device__ __half g_w2h  [VD*VD];

// ---------------- helpers ----------------
__device__ __forceinline__ uint32_t h2u(__half2 h){ return *(uint32_t*)&h; }
__device__ __forceinline__ void mma16(float* d, const uint32_t* a, const uint32_t* b){
    asm volatile("mma.sync.aligned.m16n8k16.row.col.f32.f16.f16.f32 "
        "{%0,%1,%2,%3}, {%4,%5,%6,%7}, {%8,%9}, {%0,%1,%2,%3};"
        : "+f"(d[0]), "+f"(d[1]), "+f"(d[2]), "+f"(d[3])
        : "r"(a[0]), "r"(a[1]), "r"(a[2]), "r"(a[3]), "r"(b[0]), "r"(b[1]));
}
__device__ __forceinline__ void ldsm4(uint32_t* r, uint32_t addr){
    asm volatile("ldmatrix.sync.aligned.m8n8.x4.shared.b16 {%0,%1,%2,%3}, [%4];"
        : "=r"(r[0]), "=r"(r[1]), "=r"(r[2]), "=r"(r[3]) : "r"(addr));
}

// ---------------- precompute kernels (validated) ----------------
__global__ void k_wsum9(const float* __restrict__ w) {
    int idx = blockIdx.x*256 + threadIdx.x;
    if (idx >= 9*HND*VD) return;
    int o = idx & 255, i = (idx >> 8) & 511, t = idx >> 17;
    int ty = t/3, tx = t%3;
    int kh0 = (ty==0)?1:0, kh1 = (ty==2)?1:2;
    int kw0 = (tx==0)?1:0, kw1 = (tx==2)?1:2;
    const float* wb = w + ((size_t)o*CIN + 264 + i)*9;
    float s = 0.f;
    for (int kh=kh0; kh<=kh1; kh++)
        for (int kw=kw0; kw<=kw1; kw++)
            s += wb[kh*3+kw];
    g_wsum9[idx] = s;
}

__global__ void k_hncon(const float* __restrict__ hn) {
    int idx = blockIdx.x*256 + threadIdx.x;
    if (idx >= NB*9*VD) return;
    int o = idx & 255, t = (idx >> 8) % 9, n = idx / (9*256);
    const float* hp = hn + (size_t)n*HND;
    const float* wp = g_wsum9 + (size_t)t*HND*VD + o;
    float s = 0.f;
    for (int i=0;i<HND;i++) s += hp[i]*wp[(size_t)i*VD];
    g_hncon[idx] = s;
}

__global__ void k_spbase(const float* __restrict__ w) {
    int idx = blockIdx.x*256 + threadIdx.x;
    if (idx >= PP*VD) return;
    int o = idx & 255, p = idx >> 8;
    int hh = p >> 5, ww = p & 31;
    float s = 0.f;
    for (int kh=0;kh<3;kh++) {
        int gh = hh+kh-1; if ((unsigned)gh >= 32u) continue;
        for (int kw=0;kw<3;kw++) {
            int gw = ww+kw-1; if ((unsigned)gw >= 32u) continue;
            float xmin = gw*0.0625f - 1.f, ymin = gh*0.0625f - 1.f;
            float xmax = xmin + 0.0625f,  ymax = ymin + 0.0625f;
            const float* wb = w + ((size_t)o*CIN + 256)*9 + kh*3+kw;
            s += xmin*wb[0] + ymin*wb[9] + xmax*wb[18] + ymax*wb[27]
               + 0.5f*(xmin+xmax)*wb[36] + 0.5f*(ymin+ymax)*wb[45]
               + 0.03125f*wb[54] + 0.03125f*wb[63];
        }
    }
    g_spbase[idx] = s;
}

__global__ void k_assemble() {
    int idx = blockIdx.x*256 + threadIdx.x;
    if (idx >= NB*PP*VD/4) return;
    int e = idx*4;
    int o = e & 255, p = (e >> 8) & 1023, n = e >> 18;
    int hh = p >> 5, ww = p & 31;
    int ty = (hh==0)?0:((hh==31)?2:1);
    int tx = (ww==0)?0:((ww==31)?2:1);
    float4 sp = *(const float4*)(g_spbase + (size_t)p*VD + o);
    float4 hc = *(const float4*)(g_hncon + ((size_t)(n*9 + ty*3+tx))*VD + o);
    float4 r; r.x=sp.x+hc.x; r.y=sp.y+hc.y; r.z=sp.z+hc.z; r.w=sp.w+hc.w;
    *(float4*)(g_base + (size_t)e) = r;
}

__global__ __launch_bounds__(256) void k_qh(const float* __restrict__ emb,
                                            const float* __restrict__ qw, const float* __restrict__ qb,
                                            const float* __restrict__ Wq, const float* __restrict__ bq) {
    __shared__ float es[304];
    __shared__ float qs[256];
    int n = blockIdx.x, s = blockIdx.y, c = threadIdx.x;
    for (int i=c; i<EMBD; i+=256) es[i] = emb[((size_t)n*SEQN+s)*EMBD + i];
    __syncthreads();
    float a = qb[c];
    const float* wr = qw + (size_t)c*EMBD;
    for (int e=0;e<EMBD;e++) a += es[e]*wr[e];
    qs[c] = fmaxf(a, 0.f);
    __syncthreads();
    float a2 = bq[c];
    const float* wr2 = Wq + (size_t)c*VD;
    for (int k=0;k<VD;k++) a2 += qs[k]*wr2[k];
    g_qh[((size_t)s*NB+n)*VD + c] = a2;
}

__global__ void k_repack_h(const float* __restrict__ w){
    int idx = blockIdx.x*256 + threadIdx.x;
    if (idx >= 9*VD*VD) return;
    int i = idx & 255, o = (idx >> 8) & 255, t = idx >> 16;
    g_wrh[idx] = __float2half(w[((size_t)o*CIN + i)*9 + t]);
}

__global__ void k_half(const float* __restrict__ src, __half* __restrict__ dst, int n){
    int i = blockIdx.x*256 + threadIdx.x;
    if (2*i < n){
        float2 v = *(const float2*)(src + 2*i);
        *(__half2*)(dst + 2*i) = __floats2half2_rn(v.x, v.y);
    }
}

// ---------------- transposes (once each) ----------------
__global__ __launch_bounds__(256) void k_tr_in(const float* __restrict__ src, float* __restrict__ dst){
    __shared__ float t[32][33];
    int n = blockIdx.z, c0 = blockIdx.y*32, p0 = blockIdx.x*32;
    int i = threadIdx.x >> 5, j = threadIdx.x & 31;
    for (int r=0;r<32;r+=8)
        t[i+r][j] = src[((size_t)n*VD + c0+i+r)*PP + p0 + j];
    __syncthreads();
    for (int r=0;r<32;r+=8)
        dst[((size_t)n*PP + p0+i+r)*VD + c0 + j] = t[j][i+r];
}
__global__ __launch_bounds__(256) void k_tr_out(const float* __restrict__ src, float* __restrict__ dst){
    __shared__ float t[32][33];
    int n = blockIdx.z, c0 = blockIdx.y*32, p0 = blockIdx.x*32;
    int i = threadIdx.x >> 5, j = threadIdx.x & 31;
    for (int r=0;r<32;r+=8)
        t[i+r][j] = src[((size_t)n*PP + p0+i+r)*VD + c0 + j];
    __syncthreads();
    for (int r=0;r<32;r+=8)
        dst[((size_t)n*VD + c0+i+r)*PP + p0 + j] = t[j][i+r];
}

// ---------------- fp16 HMMA GEMM, K-chunk 64, fp16 weights (R15, validated) ----------------
// MODE 0: plain GEMM, K=256.  MODE 1: conv 9-tap, W=g_wrh, resid=base.
// EPI 0:+bias  1:+bias,relu  2:+bias+resid,LN  3:EPI2+word-gate(early exit)  4:LN(relu(acc+resid))
template<int MODE, int EPI>
__global__ __launch_bounds__(512, 1) void k_tc(const float* __restrict__ A, const __half* __restrict__ W,
    const float* __restrict__ bias, const float* __restrict__ resid,
    const float* __restrict__ lng, const float* __restrict__ lnb,
    const int* __restrict__ words, int s, const float* __restrict__ fcur,
    float* __restrict__ C)
{
    extern __shared__ char smc[];
    const int tid  = threadIdx.x;
    const int lane = tid & 31;
    const int w    = tid >> 5;
    const int wm   = w & 3, wn = w >> 2;
    const int tg   = lane & 3, gp = lane >> 2;
    const int row0 = blockIdx.x*128;
    const int n    = row0 >> 10;
    const int p0   = row0 & 1023;

    if (EPI == 3){
        if (__ldg(words + s) == 0){
#pragma unroll
            for (int i=0;i<16;i++){
                int q = tid + i*512;
                size_t off = (size_t)(row0 + (q>>6))*256 + (q&63)*4;
                *(float4*)(C + off) = *(const float4*)(fcur + off);
            }
            return;
        }
    }

    float acc[2][8][4];
#pragma unroll
    for (int f=0;f<2;f++)
#pragma unroll
        for (int nf=0;nf<8;nf++)
#pragma unroll
            for (int j=0;j<4;j++) acc[f][nf][j] = 0.f;

    const int CH = MODE ? 36 : 4;
    const uint32_t smb = (uint32_t)__cvta_generic_to_shared(smc);
    const uint32_t rAoff = (uint32_t)((wm*32 + (lane&7) + ((lane>>3)&1)*8)*144 + ((lane>>4)&1)*16);
    const uint32_t rBoff = (uint32_t)((wn*64 + ((lane>>4)&1)*8 + (lane&7))*144 + ((lane>>3)&1)*16);

    auto ldgA = [&](int c, float4* r){
#pragma unroll
        for (int i=0;i<2;i++){
            int q = tid + i*512;
            int row = q>>3, c8 = q&7;
            if (MODE == 0){
                const float* base = A + (size_t)(row0+row)*256 + c*64 + c8*8;
                r[2*i]   = *(const float4*)(base);
                r[2*i+1] = *(const float4*)(base+4);
            } else {
                int tap = c >> 2, kb = c & 3;
                int dh = tap/3 - 1, dw = tap%3 - 1;
                int p = p0 + row;
                int sh = (p>>5) + dh, sw = (p&31) + dw;
                float4 v0 = make_float4(0.f,0.f,0.f,0.f), v1 = v0;
                if ((unsigned)sh < 32u && (unsigned)sw < 32u){
                    const float* base = A + ((size_t)((n<<10) + (sh<<5) + sw))*256 + kb*64 + c8*8;
                    v0 = *(const float4*)(base);
                    v1 = *(const float4*)(base+4);
                }
                r[2*i] = v0; r[2*i+1] = v1;
            }
        }
    };
    auto ldgB = [&](int c, uint4* r){
        const __half* Wb; int k0;
        if (MODE == 0){ Wb = W; k0 = c*64; }
        else { Wb = g_wrh + (size_t)(c>>2)*VD*VD; k0 = (c&3)*64; }
#pragma unroll
        for (int i=0;i<4;i++){
            int q = tid + i*512;
            r[i] = *(const uint4*)(Wb + (size_t)(q>>3)*256 + k0 + (q&7)*8);
        }
    };
    auto stsA = [&](int buf, const float4* r){
        char* As = smc + (buf ? A_DB1 : A_DB0);
#pragma unroll
        for (int i=0;i<2;i++){
            int q = tid + i*512;
            uint4 v;
            v.x = h2u(__floats2half2_rn(r[2*i].x,   r[2*i].y));
            v.y = h2u(__floats2half2_rn(r[2*i].z,   r[2*i].w));
            v.z = h2u(__floats2half2_rn(r[2*i+1].x, r[2*i+1].y));
            v.w = h2u(__floats2half2_rn(r[2*i+1].z, r[2*i+1].w));
            *(uint4*)(As + (q>>3)*144 + (q&7)*16) = v;
        }
    };
    auto stsB = [&](int buf, const uint4* r){
        char* Bs = smc + (buf ? B_DB1 : B_DB0);
#pragma unroll
        for (int i=0;i<4;i++){
            int q = tid + i*512;
            *(uint4*)(Bs + (q>>3)*144 + (q&7)*16) = r[i];
        }
    };
    auto compute = [&](int buf){
        uint32_t As = smb + (buf ? A_DB1 : A_DB0);
        uint32_t Bs = smb + (buf ? B_DB1 : B_DB0);
#pragma unroll
        for (int kk=0; kk<4; kk++){
            uint32_t a0[4], a1[4];
            ldsm4(a0, As + rAoff + kk*32);
            ldsm4(a1, As + rAoff + 16*144 + kk*32);
#pragma unroll
            for (int nfp=0; nfp<4; nfp++){
                uint32_t b4[4];
                ldsm4(b4, Bs + rBoff + nfp*16*144 + kk*32);
                mma16(acc[0][2*nfp+0], a0, &b4[0]);
                mma16(acc[1][2*nfp+0], a1, &b4[0]);
                mma16(acc[0][2*nfp+1], a0, &b4[2]);
                mma16(acc[1][2*nfp+1], a1, &b4[2]);
            }
        }
    };

    {
        float4 ra[4]; uint4 rb[4];
        ldgA(0, ra); ldgB(0, rb);
        stsA(0, ra); stsB(0, rb);
    }
    __syncthreads();
    for (int c=0; c<CH; c++){
        float4 ra[4]; uint4 rb[4];
        if (c+1 < CH){ ldgA(c+1, ra); ldgB(c+1, rb); }
        compute(c&1);
        if (c+1 < CH){ stsA((c+1)&1, ra); stsB((c+1)&1, rb); }
        __syncthreads();
    }

    if (EPI <= 1){
#pragma unroll
        for (int f=0;f<2;f++)
#pragma unroll
        for (int nf=0;nf<8;nf++){
            int colb = wn*64 + nf*8 + 2*tg;
            float2 bb = *(const float2*)(bias + colb);
#pragma unroll
            for (int h=0;h<2;h++){
                int row = row0 + wm*32 + f*16 + h*8 + gp;
                float2 o;
                o.x = acc[f][nf][2*h+0] + bb.x;
                o.y = acc[f][nf][2*h+1] + bb.y;
                if (EPI == 1){ o.x = fmaxf(o.x,0.f); o.y = fmaxf(o.y,0.f); }
                *(float2*)(C + (size_t)row*256 + colb) = o;
            }
        }
        return;
    }

#pragma unroll
    for (int f=0;f<2;f++)
#pragma unroll
    for (int nf=0;nf<8;nf++){
        int colb = wn*64 + nf*8 + 2*tg;
        float2 bb = make_float2(0.f, 0.f);
        if (EPI != 4) bb = *(const float2*)(bias + colb);
#pragma unroll
        for (int h=0;h<2;h++){
            int row = row0 + wm*32 + f*16 + h*8 + gp;
            float2 rr = *(const float2*)(resid + (size_t)row*256 + colb);
            float vx = acc[f][nf][2*h+0] + bb.x + rr.x;
            float vy = acc[f][nf][2*h+1] + bb.y + rr.y;
            if (EPI == 4){ vx = fmaxf(vx, 0.f); vy = fmaxf(vy, 0.f); }
            acc[f][nf][2*h+0] = vx;
            acc[f][nf][2*h+1] = vy;
        }
    }
    float2* red = (float2*)smc;
#pragma unroll
    for (int f=0;f<2;f++)
#pragma unroll
    for (int h=0;h<2;h++){
        float su = 0.f, sq = 0.f;
#pragma unroll
        for (int nf=0;nf<8;nf++){
            float vx = acc[f][nf][2*h+0], vy = acc[f][nf][2*h+1];
            su += vx + vy;
            sq += vx*vx + vy*vy;
        }
        su += __shfl_xor_sync(0xffffffffu, su, 1);
        sq += __shfl_xor_sync(0xffffffffu, sq, 1);
        su += __shfl_xor_sync(0xffffffffu, su, 2);
        sq += __shfl_xor_sync(0xffffffffu, sq, 2);
        if (tg == 0){
            int rloc = wm*32 + f*16 + h*8 + gp;
            red[wn*128 + rloc] = make_float2(su, sq);
        }
    }
    __syncthreads();
#pragma unroll
    for (int f=0;f<2;f++)
#pragma unroll
    for (int h=0;h<2;h++){
        int rloc = wm*32 + f*16 + h*8 + gp;
        float S = 0.f, Q = 0.f;
#pragma unroll
        for (int w4=0;w4<4;w4++){
            float2 v = red[w4*128 + rloc];
            S += v.x; Q += v.y;
        }
        float m  = S*(1.f/256.f);
        float rs = rsqrtf(Q*(1.f/256.f) - m*m + 1e-5f);
        int row = row0 + rloc;
#pragma unroll
        for (int nf=0;nf<8;nf++){
            int colb = wn*64 + nf*8 + 2*tg;
            float2 g2 = *(const float2*)(lng + colb);
            float2 b2 = *(const float2*)(lnb + colb);
            float2 o;
            o.x = (acc[f][nf][2*h+0]-m)*rs*g2.x + b2.x;
            o.y = (acc[f][nf][2*h+1]-m)*rs*g2.y + b2.y;
            *(float2*)(C + (size_t)row*256 + colb) = o;
        }
    }
}

// ---------------- fused K+V projection: resident A, single wave ----------------
__global__ __launch_bounds__(512, 1) void k_kv(const float* __restrict__ A,
    const float* __restrict__ bk, const float* __restrict__ bv)
{
    extern __shared__ char smc[];
    const int tid  = threadIdx.x;
    const int lane = tid & 31;
    const int w    = tid >> 5;
    const int wm   = w & 3, wn = w >> 2;
    const int tg   = lane & 3, gp = lane >> 2;
    const int row0 = blockIdx.x*128;
    const uint32_t smb = (uint32_t)__cvta_generic_to_shared(smc);
    const uint32_t rAoff = (uint32_t)((wm*32 + (lane&7) + ((lane>>3)&1)*8)*528 + ((lane>>4)&1)*16);
    const uint32_t rBoff = (uint32_t)((wn*64 + ((lane>>4)&1)*8 + (lane&7))*144 + ((lane>>3)&1)*16);

    // resident A: 128 rows x 256 halves, 528B stride (validated conflict-free, R9)
#pragma unroll
    for (int i=0;i<8;i++){
        int q = tid + i*512;               // 4096 slots
        int row = q>>5, c8 = q&31;
        const float* base = A + (size_t)(row0+row)*256 + c8*8;
        float4 v0 = *(const float4*)(base);
        float4 v1 = *(const float4*)(base+4);
        uint4 hv;
        hv.x = h2u(__floats2half2_rn(v0.x, v0.y));
        hv.y = h2u(__floats2half2_rn(v0.z, v0.w));
        hv.z = h2u(__floats2half2_rn(v1.x, v1.y));
        hv.w = h2u(__floats2half2_rn(v1.z, v1.w));
        *(uint4*)(smc + row*528 + c8*16) = hv;
    }

    float acc[2][8][4];
#pragma unroll
    for (int f=0;f<2;f++)
#pragma unroll
        for (int nf=0;nf<8;nf++)
#pragma unroll
            for (int j=0;j<4;j++) acc[f][nf][j] = 0.f;

    uint4 rb[4];
    auto ldgB = [&](const __half* Wb, int c){
#pragma unroll
        for (int i=0;i<4;i++){
            int q = tid + i*512;
            rb[i] = *(const uint4*)(Wb + (size_t)(q>>3)*256 + c*64 + (q&7)*8);
        }
    };
    auto stsB = [&](int buf){
        char* Bs = smc + (buf ? KV_B1 : KV_B0);
#pragma unroll
        for (int i=0;i<4;i++){
            int q = tid + i*512;
            *(uint4*)(Bs + (q>>3)*144 + (q&7)*16) = rb[i];
        }
    };
    auto compute = [&](int c, int buf){
        uint32_t As = smb + c*128;          // chunk c = bytes [c*128, c*128+128)
        uint32_t Bs = smb + (buf ? KV_B1 : KV_B0);
#pragma unroll
        for (int kk=0; kk<4; kk++){
            uint32_t a0[4], a1[4];
            ldsm4(a0, As + rAoff + kk*32);
            ldsm4(a1, As + rAoff + 16*528 + kk*32);
#pragma unroll
            for (int nfp=0; nfp<4; nfp++){
                uint32_t b4[4];
                ldsm4(b4, Bs + rBoff + nfp*16*144 + kk*32);
                mma16(acc[0][2*nfp+0], a0, &b4[0]);
                mma16(acc[1][2*nfp+0], a1, &b4[0]);
                mma16(acc[0][2*nfp+1], a0, &b4[2]);
                mma16(acc[1][2*nfp+1], a1, &b4[2]);
            }
        }
    };
    auto epilogue = [&](float* C, const float* bias){
#pragma unroll
        for (int f=0;f<2;f++)
#pragma unroll
        for (int nf=0;nf<8;nf++){
            int colb = wn*64 + nf*8 + 2*tg;
            float2 bb = *(const float2*)(bias + colb);
#pragma unroll
            for (int h=0;h<2;h++){
                int row = row0 + wm*32 + f*16 + h*8 + gp;
                *(float2*)(C + (size_t)row*256 + colb) =
                    make_float2(acc[f][nf][2*h+0] + bb.x, acc[f][nf][2*h+1] + bb.y);
            }
        }
    };

    ldgB(g_wkh, 0);
    stsB(0);
    __syncthreads();
    for (int t=0; t<8; t++){
        if (t+1 < 8) ldgB((t+1 < 4) ? g_wkh : g_wvh, (t+1)&3);
        compute(t&3, t&1);
        if (t+1 < 8) stsB((t+1)&1);
        __syncthreads();
        if (t == 3){
            epilogue(g_kh, bk);
#pragma unroll
            for (int f=0;f<2;f++)
#pragma unroll
            for (int nf=0;nf<8;nf++)
#pragma unroll
            for (int j=0;j<4;j++) acc[f][nf][j] = 0.f;
        }
    }
    epilogue(g_vv, bv);
}

// ---------------- attention (vectorized float4, validated R12) ----------------
#define KPAD 260
__global__ __launch_bounds__(256) void k_attn(int s) {
    __shared__ float ks[16*KPAD];
    __shared__ float vs[16*KPAD];
    __shared__ float sc[512];
    int p = blockIdx.x, tid = threadIdx.x;
    for (int idx=tid; idx<16*64; idx+=256) {
        int m = idx >> 6, c4 = idx & 63;
        size_t ga = ((size_t)(m*PP + p))*VD + c4*4;
        *(float4*)(ks + m*KPAD + c4*4) = *(const float4*)(g_kh + ga);
        *(float4*)(vs + m*KPAD + c4*4) = *(const float4*)(g_vv + ga);
    }
    __syncthreads();
    const float scale = 0.08838834764831845f;
#pragma unroll
    for (int rep=0; rep<2; rep++) {
        int si = tid + rep*256;
        int h = si >> 8, l = (si >> 4) & 15, m = si & 15;
        const float4* qp = (const float4*)(g_qh + ((size_t)(s*NB + l))*VD + h*DHD);
        const float4* kp = (const float4*)(ks + m*KPAD + h*DHD);
        float d = 0.f;
#pragma unroll
        for (int k=0;k<32;k++){
            float4 q4 = qp[k], k4 = kp[k];
            d += q4.x*k4.x + q4.y*k4.y + q4.z*k4.z + q4.w*k4.w;
        }
        sc[si] = d*scale;
    }
    __syncthreads();
    if (tid < 32) {
        float* r = sc + tid*16;
        float mx = r[0];
#pragma unroll
        for (int m=1;m<16;m++) mx = fmaxf(mx, r[m]);
        float su=0.f;
#pragma unroll
        for (int m=0;m<16;m++){ float e = __expf(r[m]-mx); r[m]=e; su+=e; }
        float inv = 1.f/su;
#pragma unroll
        for (int m=0;m<16;m++) r[m]*=inv;
    }
    __syncthreads();
    for (int idx=tid; idx<1024; idx+=256) {
        int l = idx >> 6, c4 = idx & 63;
        int h = c4 >> 5;
        const float* a = sc + (h*16+l)*16;
        float4 o4 = make_float4(0.f,0.f,0.f,0.f);
#pragma unroll
        for (int m=0;m<16;m++){
            float am = a[m];
            float4 v4 = *(const float4*)(vs + m*KPAD + c4*4);
            o4.x += am*v4.x; o4.y += am*v4.y; o4.z += am*v4.z; o4.w += am*v4.w;
        }
        *(float4*)(g_o + ((size_t)(l*PP+p))*VD + c4*4) = o4;
    }
}

// ---------------- launch ----------------
extern "C" void kernel_launch(void* const* d_in, const int* in_sizes, int n_in,
                              void* d_out, int out_size) {
    const float* hn         = (const float*)d_in[1];
    const float* feature    = (const float*)d_in[2];
    const float* embedding  = (const float*)d_in[3];
    const int*   words      = (const int*)  d_in[4];
    const float* qconv_w    = (const float*)d_in[5];
    const float* qconv_b    = (const float*)d_in[6];
    const float* mconv_w    = (const float*)d_in[7];
    const float* mnorm_g    = (const float*)d_in[8];
    const float* mnorm_b    = (const float*)d_in[9];
    const float* in_proj_w  = (const float*)d_in[10];
    const float* in_proj_b  = (const float*)d_in[11];
    const float* out_proj_w = (const float*)d_in[12];
    const float* out_proj_b = (const float*)d_in[13];
    const float* norm_g     = (const float*)d_in[14];
    const float* norm_b     = (const float*)d_in[15];
    const float* lin1_w     = (const float*)d_in[16];
    const float* lin1_b     = (const float*)d_in[17];
    const float* lin2_w     = (const float*)d_in[18];
    const float* lin2_b     = (const float*)d_in[19];
    const float* normf_g    = (const float*)d_in[20];
    const float* normf_b    = (const float*)d_in[21];

    cudaFuncSetAttribute(k_tc<0,1>, cudaFuncAttributeMaxDynamicSharedMemorySize, SMEM_BYTES);
    cudaFuncSetAttribute(k_tc<0,2>, cudaFuncAttributeMaxDynamicSharedMemorySize, SMEM_BYTES);
    cudaFuncSetAttribute(k_tc<0,3>, cudaFuncAttributeMaxDynamicSharedMemorySize, SMEM_BYTES);
    cudaFuncSetAttribute(k_tc<1,4>, cudaFuncAttributeMaxDynamicSharedMemorySize, SMEM_BYTES);
    cudaFuncSetAttribute(k_kv,      cudaFuncAttributeMaxDynamicSharedMemorySize, KV_SMEM);

    float *fA, *fB, *p_t, *p_kh, *p_o, *p_fea1, *p_base;
    cudaGetSymbolAddress((void**)&fA,     g_featA);
    cudaGetSymbolAddress((void**)&fB,     g_featB);
    cudaGetSymbolAddress((void**)&p_t,    g_t);
    cudaGetSymbolAddress((void**)&p_kh,   g_kh);
    cudaGetSymbolAddress((void**)&p_o,    g_o);
    cudaGetSymbolAddress((void**)&p_fea1, g_fea1);
    cudaGetSymbolAddress((void**)&p_base, g_base);
    __half *p_wkh, *p_wvh, *p_woh, *p_w1h, *p_w2h;
    cudaGetSymbolAddress((void**)&p_wkh,  g_wkh);
    cudaGetSymbolAddress((void**)&p_wvh,  g_wvh);
    cudaGetSymbolAddress((void**)&p_woh,  g_woh);
    cudaGetSymbolAddress((void**)&p_w1h,  g_w1h);
    cudaGetSymbolAddress((void**)&p_w2h,  g_w2h);

    // one-time precompute
    k_wsum9    <<<(9*HND*VD+255)/256, 256>>>(mconv_w);
    k_spbase   <<<(PP*VD+255)/256,    256>>>(mconv_w);
    k_hncon    <<<(NB*9*VD+255)/256,  256>>>(hn);
    k_assemble <<<(NB*PP*VD/4+255)/256, 256>>>();
    k_qh       <<<dim3(NB,SEQN), 256>>>(embedding, qconv_w, qconv_b, in_proj_w, in_proj_b);
    k_repack_h <<<(9*VD*VD+255)/256,  256>>>(mconv_w);
    k_half     <<<128,256>>>(in_proj_w + VD*VD,   p_wkh, VD*VD);
    k_half     <<<128,256>>>(in_proj_w + 2*VD*VD, p_wvh, VD*VD);
    k_half     <<<128,256>>>(out_proj_w,          p_woh, VD*VD);
    k_half     <<<128,256>>>(lin1_w,              p_w1h, VD*VD);
    k_half     <<<128,256>>>(lin2_w,              p_w2h, VD*VD);
    k_tr_in    <<<dim3(32,8,NB), 256>>>(feature, fA);

    for (int s=0; s<SEQN; s++) {
        const float* fin = (s&1) ? fB : fA;
        float* fout      = (s&1) ? fA : fB;

        k_tc<1,4><<<128,512,SMEM_BYTES>>>(fin, nullptr, nullptr, p_base,
                                          mnorm_g, mnorm_b, nullptr, 0, nullptr, p_t);
        k_kv   <<<128,512,KV_SMEM>>>(p_t, in_proj_b + VD, in_proj_b + 2*VD);
        k_attn <<<PP,256>>>(s);
        k_tc<0,2><<<128,512,SMEM_BYTES>>>(p_o, p_woh, out_proj_b,
                                          p_t, norm_g, norm_b, nullptr, 0, nullptr, p_fea1);
        k_tc<0,1><<<128,512,SMEM_BYTES>>>(p_fea1, p_w1h, lin1_b,
                                          nullptr, nullptr, nullptr, nullptr, 0, nullptr, p_kh);
        k_tc<0,3><<<128,512,SMEM_BYTES>>>(p_kh, p_w2h, lin2_b,
                                          p_fea1, normf_g, normf_b, words, s, fin, fout);
    }
    k_tr_out<<<dim3(32,8,NB), 256>>>(fA, (float*)d_out);
}